// round 2
// baseline (speedup 1.0000x reference)
#include <cuda_runtime.h>
#include <cstddef>

// Problem constants
#define BB   32
#define TT   512
#define DIN  256
#define HH   1024
#define G3   3072            // 3*H
#define DOUT 256
#define MTOT (BB * TT)       // 16384

// ---------------------------------------------------------------------------
// Static device scratch (the sanctioned no-alloc mechanism)
// ---------------------------------------------------------------------------
__device__ float    g_gx[(size_t)MTOT * G3];   // reused for gx0 then gx1 (201 MB)
__device__ float    g_out0[(size_t)MTOT * HH]; // layer-0 outputs (64 MB)
__device__ float    g_ha[BB * HH];
__device__ float    g_hb[BB * HH];
__device__ unsigned g_bar;

// ---------------------------------------------------------------------------
// Packed fp32x2 helpers (Blackwell dual-rate fp32 path; scalar FFMA is rt=2)
// ---------------------------------------------------------------------------
__device__ __forceinline__ unsigned long long pack_dup(float a) {
    unsigned long long r;
    asm("mov.b64 %0, {%1, %1};" : "=l"(r) : "f"(a));
    return r;
}
__device__ __forceinline__ void fma2(unsigned long long& c,
                                     unsigned long long a,
                                     unsigned long long b) {
    asm("fma.rn.f32x2 %0, %1, %2, %0;" : "+l"(c) : "l"(a), "l"(b));
}
__device__ __forceinline__ float2 unpack2(unsigned long long v) {
    float2 f;
    asm("mov.b64 {%0, %1}, %2;" : "=f"(f.x), "=f"(f.y) : "l"(v));
    return f;
}

// ---------------------------------------------------------------------------
// GEMM: C[M,N] = A[M,K] @ W[N,K]^T + bias[N]
// BM=BN=128, BK=16, 256 threads, 8x8 register tile via f32x2.
// M,N multiples of 128; K multiple of 16 (holds for 256/1024).
// ---------------------------------------------------------------------------
__global__ __launch_bounds__(256) void gemm_bias_kernel(
    const float* __restrict__ A, const float* __restrict__ W,
    const float* __restrict__ bias, float* __restrict__ C,
    int M, int N, int K)
{
    __shared__ __align__(16) float As[16][128];
    __shared__ __align__(16) float Ws[16][128];

    const int tid = threadIdx.x;
    const int m0 = blockIdx.y * 128;
    const int n0 = blockIdx.x * 128;
    const int tx = tid & 15;
    const int ty = tid >> 4;

    unsigned long long acc[8][4];
#pragma unroll
    for (int i = 0; i < 8; i++)
#pragma unroll
        for (int j = 0; j < 4; j++) acc[i][j] = 0ULL;

    const int lrow = tid >> 2;   // 0..63
    const int lc4  = tid & 3;    // 0..3

    for (int k0 = 0; k0 < K; k0 += 16) {
#pragma unroll
        for (int r = 0; r < 2; r++) {
            int row = lrow + r * 64;
            float4 va = *(const float4*)&A[(size_t)(m0 + row) * K + k0 + lc4 * 4];
            As[lc4 * 4 + 0][row] = va.x; As[lc4 * 4 + 1][row] = va.y;
            As[lc4 * 4 + 2][row] = va.z; As[lc4 * 4 + 3][row] = va.w;
            float4 vw = *(const float4*)&W[(size_t)(n0 + row) * K + k0 + lc4 * 4];
            Ws[lc4 * 4 + 0][row] = vw.x; Ws[lc4 * 4 + 1][row] = vw.y;
            Ws[lc4 * 4 + 2][row] = vw.z; Ws[lc4 * 4 + 3][row] = vw.w;
        }
        __syncthreads();
#pragma unroll
        for (int k = 0; k < 16; k++) {
            float4 a0 = *(const float4*)&As[k][ty * 8];
            float4 a1 = *(const float4*)&As[k][ty * 8 + 4];
            ulonglong2 b0 = *(const ulonglong2*)&Ws[k][tx * 8];
            ulonglong2 b1 = *(const ulonglong2*)&Ws[k][tx * 8 + 4];
            unsigned long long bp[4] = {b0.x, b0.y, b1.x, b1.y};
            float av[8] = {a0.x, a0.y, a0.z, a0.w, a1.x, a1.y, a1.z, a1.w};
#pragma unroll
            for (int i = 0; i < 8; i++) {
                unsigned long long ap = pack_dup(av[i]);
#pragma unroll
                for (int j = 0; j < 4; j++) fma2(acc[i][j], ap, bp[j]);
            }
        }
        __syncthreads();
    }

#pragma unroll
    for (int i = 0; i < 8; i++) {
        int m = m0 + ty * 8 + i;
#pragma unroll
        for (int j = 0; j < 4; j++) {
            float2 v = unpack2(acc[i][j]);
            int n = n0 + tx * 8 + j * 2;
            C[(size_t)m * N + n]     = v.x + bias[n];
            C[(size_t)m * N + n + 1] = v.y + bias[n + 1];
        }
    }
}

// ---------------------------------------------------------------------------
// Persistent GRU scan. grid=128 CTAs x 256 threads; warp w of block c owns
// neuron j = c*8+w, with its 3 gate weight rows (3KB) register-stationary
// across all 512 timesteps. Per step: per batch b, dot(h[b,:], w_row) via
// f32x2, warp butterfly reduce, lane0 does the gate math and stores h_new.
// Grid barrier (release-fence + atomic + L2 spin) per timestep.
// ---------------------------------------------------------------------------
__global__ __launch_bounds__(256) void gru_scan_kernel(
    const float* __restrict__ gx, const float* __restrict__ w_hh,
    const float* __restrict__ b_hh, float* __restrict__ ha,
    float* __restrict__ hb, float* __restrict__ out, int writeOut)
{
    const int warp = threadIdx.x >> 5;
    const int lane = threadIdx.x & 31;
    const int j = blockIdx.x * 8 + warp;
    const unsigned nCta = gridDim.x;

    // Load weights once (lane owns k in {i*128 + lane*4 .. +3}, i<8)
    ulonglong2 wv[3][8];
#pragma unroll
    for (int g = 0; g < 3; g++)
#pragma unroll
        for (int i = 0; i < 8; i++)
            wv[g][i] = *(const ulonglong2*)&w_hh[(size_t)(g * HH + j) * HH + i * 128 + lane * 4];

    const float br = b_hh[0 * HH + j];
    const float bz = b_hh[1 * HH + j];
    const float bn = b_hh[2 * HH + j];

#pragma unroll 1
    for (int t = 0; t < TT; t++) {
        const float* hc = (t & 1) ? hb : ha;
        float*       hn = (t & 1) ? ha : hb;

#pragma unroll 1
        for (int b = 0; b < BB; b++) {
            unsigned long long ar0 = 0, ar1 = 0, az0 = 0, az1 = 0, an0 = 0, an1 = 0;
#pragma unroll
            for (int i = 0; i < 8; i++) {
                ulonglong2 h2 = __ldcg((const ulonglong2*)&hc[b * HH + i * 128 + lane * 4]);
                fma2(ar0, h2.x, wv[0][i].x); fma2(ar1, h2.y, wv[0][i].y);
                fma2(az0, h2.x, wv[1][i].x); fma2(az1, h2.y, wv[1][i].y);
                fma2(an0, h2.x, wv[2][i].x); fma2(an1, h2.y, wv[2][i].y);
            }
            float2 f;
            f = unpack2(ar0); float sr = f.x + f.y; f = unpack2(ar1); sr += f.x + f.y;
            f = unpack2(az0); float sz = f.x + f.y; f = unpack2(az1); sz += f.x + f.y;
            f = unpack2(an0); float sn = f.x + f.y; f = unpack2(an1); sn += f.x + f.y;
#pragma unroll
            for (int off = 16; off > 0; off >>= 1) {
                sr += __shfl_xor_sync(0xffffffffu, sr, off);
                sz += __shfl_xor_sync(0xffffffffu, sz, off);
                sn += __shfl_xor_sync(0xffffffffu, sn, off);
            }
            if (lane == 0) {
                size_t gbase = ((size_t)b * TT + t) * G3 + j;
                float xr = __ldg(&gx[gbase]);
                float xz = __ldg(&gx[gbase + HH]);
                float xn = __ldg(&gx[gbase + 2 * HH]);
                float r  = 1.f / (1.f + __expf(-(xr + sr + br)));
                float z  = 1.f / (1.f + __expf(-(xz + sz + bz)));
                float nn = tanhf(xn + r * (sn + bn));
                float hold = __ldcg(&hc[b * HH + j]);
                float hnew = (1.f - z) * nn + z * hold;
                __stcg(&hn[b * HH + j], hnew);
                if (writeOut) out[((size_t)b * TT + t) * HH + j] = hnew;
            }
        }

        // ---- grid barrier: release all h writes, arrive, spin on L2 ----
        __threadfence();
        __syncthreads();
        if (threadIdx.x == 0) {
            atomicAdd(&g_bar, 1u);
            unsigned target = nCta * (unsigned)(t + 1);
            while (*((volatile unsigned*)&g_bar) < target) { }
        }
        __syncthreads();
    }
}

// ---------------------------------------------------------------------------
// Final FC: logits = sigmoid(h_last1 @ fc_w^T + fc_b). One warp per output.
// ---------------------------------------------------------------------------
__global__ __launch_bounds__(256) void fc_kernel(
    const float* __restrict__ h, const float* __restrict__ w,
    const float* __restrict__ bias, float* __restrict__ outp)
{
    int gw   = (int)((blockIdx.x * blockDim.x + threadIdx.x) >> 5);
    int lane = threadIdx.x & 31;
    if (gw >= BB * DOUT) return;
    int m = gw >> 8;
    int o = gw & 255;
    float acc = 0.f;
#pragma unroll
    for (int i = 0; i < 8; i++) {
        float4 hv = *(const float4*)&h[m * HH + i * 128 + lane * 4];
        float4 wv = *(const float4*)&w[o * HH + i * 128 + lane * 4];
        acc += hv.x * wv.x + hv.y * wv.y + hv.z * wv.z + hv.w * wv.w;
    }
#pragma unroll
    for (int off = 16; off > 0; off >>= 1)
        acc += __shfl_xor_sync(0xffffffffu, acc, off);
    if (lane == 0)
        outp[m * DOUT + o] = 1.f / (1.f + __expf(-(acc + bias[o])));
}

// ---------------------------------------------------------------------------
// Orchestration (graph-capturable: kernels + async memset/memcpy only)
// ---------------------------------------------------------------------------
extern "C" void kernel_launch(void* const* d_in, const int* in_sizes, int n_in,
                              void* d_out, int out_size)
{
    const float* input = (const float*)d_in[0];
    const float* w_ih0 = (const float*)d_in[1];
    const float* w_hh0 = (const float*)d_in[2];
    const float* b_ih0 = (const float*)d_in[3];
    const float* b_hh0 = (const float*)d_in[4];
    const float* w_ih1 = (const float*)d_in[5];
    const float* w_hh1 = (const float*)d_in[6];
    const float* b_ih1 = (const float*)d_in[7];
    const float* b_hh1 = (const float*)d_in[8];
    const float* fc_w  = (const float*)d_in[9];
    const float* fc_b  = (const float*)d_in[10];
    float* outp = (float*)d_out;

    float *gx, *out0, *ha, *hb;
    unsigned* bar;
    cudaGetSymbolAddress((void**)&gx,   g_gx);
    cudaGetSymbolAddress((void**)&out0, g_out0);
    cudaGetSymbolAddress((void**)&ha,   g_ha);
    cudaGetSymbolAddress((void**)&hb,   g_hb);
    cudaGetSymbolAddress((void**)&bar,  g_bar);

    dim3 ggrid(G3 / 128, MTOT / 128);   // 24 x 128

    // Layer 0 input projection: gx0 = input @ w_ih0^T + b_ih0
    gemm_bias_kernel<<<ggrid, 256>>>(input, w_ih0, b_ih0, gx, MTOT, G3, DIN);

    // Layer 0 scan
    cudaMemsetAsync(ha, 0, BB * HH * sizeof(float));
    cudaMemsetAsync(bar, 0, sizeof(unsigned));
    gru_scan_kernel<<<128, 256>>>(gx, w_hh0, b_hh0, ha, hb, out0, 1);
    // T=512 even -> final h lands in ha
    cudaMemcpyAsync(outp + BB * DOUT, ha, BB * HH * sizeof(float),
                    cudaMemcpyDeviceToDevice);

    // Layer 1 input projection: gx1 = out0 @ w_ih1^T + b_ih1
    gemm_bias_kernel<<<ggrid, 256>>>(out0, w_ih1, b_ih1, gx, MTOT, G3, HH);

    // Layer 1 scan (out1[:, -1, :] == h_last1, so no per-step output needed)
    cudaMemsetAsync(ha, 0, BB * HH * sizeof(float));
    cudaMemsetAsync(bar, 0, sizeof(unsigned));
    gru_scan_kernel<<<128, 256>>>(gx, w_hh1, b_hh1, ha, hb, nullptr, 0);
    cudaMemcpyAsync(outp + BB * DOUT + BB * HH, ha, BB * HH * sizeof(float),
                    cudaMemcpyDeviceToDevice);

    // logits = sigmoid(h_last1 @ fc_w^T + fc_b)
    fc_kernel<<<(BB * DOUT * 32) / 256, 256>>>(ha, fc_w, fc_b, outp);
}

// round 3
// speedup vs baseline: 5.3001x; 5.3001x over previous
#include <cuda_runtime.h>
#include <cstddef>

// Problem constants
#define BB   32
#define TT   512
#define DIN  256
#define HH   1024
#define G3   3072            // 3*H
#define DOUT 256
#define MTOT (BB * TT)       // 16384

// ---------------------------------------------------------------------------
// Static device scratch
// ---------------------------------------------------------------------------
__device__ float    g_gx[(size_t)MTOT * G3];   // reused for gx0 then gx1
__device__ float    g_out0[(size_t)MTOT * HH]; // layer-0 outputs
__device__ float    g_ha[BB * HH];
__device__ float    g_hb[BB * HH];
__device__ unsigned g_bar;

// ---------------------------------------------------------------------------
// Packed fp32x2 helpers
// ---------------------------------------------------------------------------
__device__ __forceinline__ unsigned long long pack_dup(float a) {
    unsigned long long r;
    asm("mov.b64 %0, {%1, %1};" : "=l"(r) : "f"(a));
    return r;
}
__device__ __forceinline__ void fma2(unsigned long long& c,
                                     unsigned long long a,
                                     unsigned long long b) {
    asm("fma.rn.f32x2 %0, %1, %2, %0;" : "+l"(c) : "l"(a), "l"(b));
}
__device__ __forceinline__ float2 unpack2(unsigned long long v) {
    float2 f;
    asm("mov.b64 {%0, %1}, %2;" : "=f"(f.x), "=f"(f.y) : "l"(v));
    return f;
}

// ---------------------------------------------------------------------------
// GEMM: C[M,N] = A[M,K] @ W[N,K]^T + bias[N]   (unchanged from R1 — ~1 ms total)
// ---------------------------------------------------------------------------
__global__ __launch_bounds__(256) void gemm_bias_kernel(
    const float* __restrict__ A, const float* __restrict__ W,
    const float* __restrict__ bias, float* __restrict__ C,
    int M, int N, int K)
{
    __shared__ __align__(16) float As[16][128];
    __shared__ __align__(16) float Ws[16][128];

    const int tid = threadIdx.x;
    const int m0 = blockIdx.y * 128;
    const int n0 = blockIdx.x * 128;
    const int tx = tid & 15;
    const int ty = tid >> 4;

    unsigned long long acc[8][4];
#pragma unroll
    for (int i = 0; i < 8; i++)
#pragma unroll
        for (int j = 0; j < 4; j++) acc[i][j] = 0ULL;

    const int lrow = tid >> 2;
    const int lc4  = tid & 3;

    for (int k0 = 0; k0 < K; k0 += 16) {
#pragma unroll
        for (int r = 0; r < 2; r++) {
            int row = lrow + r * 64;
            float4 va = *(const float4*)&A[(size_t)(m0 + row) * K + k0 + lc4 * 4];
            As[lc4 * 4 + 0][row] = va.x; As[lc4 * 4 + 1][row] = va.y;
            As[lc4 * 4 + 2][row] = va.z; As[lc4 * 4 + 3][row] = va.w;
            float4 vw = *(const float4*)&W[(size_t)(n0 + row) * K + k0 + lc4 * 4];
            Ws[lc4 * 4 + 0][row] = vw.x; Ws[lc4 * 4 + 1][row] = vw.y;
            Ws[lc4 * 4 + 2][row] = vw.z; Ws[lc4 * 4 + 3][row] = vw.w;
        }
        __syncthreads();
#pragma unroll
        for (int k = 0; k < 16; k++) {
            float4 a0 = *(const float4*)&As[k][ty * 8];
            float4 a1 = *(const float4*)&As[k][ty * 8 + 4];
            ulonglong2 b0 = *(const ulonglong2*)&Ws[k][tx * 8];
            ulonglong2 b1 = *(const ulonglong2*)&Ws[k][tx * 8 + 4];
            unsigned long long bp[4] = {b0.x, b0.y, b1.x, b1.y};
            float av[8] = {a0.x, a0.y, a0.z, a0.w, a1.x, a1.y, a1.z, a1.w};
#pragma unroll
            for (int i = 0; i < 8; i++) {
                unsigned long long ap = pack_dup(av[i]);
#pragma unroll
                for (int j = 0; j < 4; j++) fma2(acc[i][j], ap, bp[j]);
            }
        }
        __syncthreads();
    }

#pragma unroll
    for (int i = 0; i < 8; i++) {
        int m = m0 + ty * 8 + i;
#pragma unroll
        for (int j = 0; j < 4; j++) {
            float2 v = unpack2(acc[i][j]);
            int n = n0 + tx * 8 + j * 2;
            C[(size_t)m * N + n]     = v.x + bias[n];
            C[(size_t)m * N + n + 1] = v.y + bias[n + 1];
        }
    }
}

// ---------------------------------------------------------------------------
// GRU scan v2: 128 CTAs x 512 threads, persistent, grid barrier per step.
//   smem: full h state (32x1024 f32 = 128KB) staged once per step,
//         plus partial-sum buffer [2 khalf][3 gate][8 neuron][32 batch].
//   Warp w: neuron nw = w>>1 (j = blockIdx*8+nw), k-half kh = w&1.
//   Weights (3 gates x 512 k) register-stationary: 12 ulonglong2 = 48 regs.
//   Inner loop: 4 batches in flight -> 12 independent fma2 chains (ILP),
//   all h reads from smem (LDS, 29cyc), gx prefetched at step start.
// ---------------------------------------------------------------------------
#define SCAN_THREADS 512
#define SUM_OFF (BB * HH)                       // floats
#define SMEM_FLOATS (BB * HH + 2 * 3 * 8 * 32)  // 131072 + 6144 bytes

__global__ __launch_bounds__(SCAN_THREADS) void gru_scan_kernel(
    const float* __restrict__ gx, const float* __restrict__ w_hh,
    const float* __restrict__ b_hh, float* __restrict__ ha,
    float* __restrict__ hb, float* __restrict__ out, int writeOut)
{
    extern __shared__ __align__(16) float sh[];
    float* sh_h   = sh;            // [BB][HH]
    float* sh_sum = sh + SUM_OFF;  // [2][3][8][32]

    const int tid  = threadIdx.x;
    const int warp = tid >> 5;
    const int lane = tid & 31;
    const int nw   = warp >> 1;          // neuron within CTA (0..7)
    const int kh   = warp & 1;           // k-half
    const int j0   = blockIdx.x * 8;
    const int j    = j0 + nw;
    const unsigned nCta = gridDim.x;

    // Register-stationary weights: w_hh[(g*HH+j)*HH + kh*512 + i*128 + lane*4]
    ulonglong2 wv[3][4];
#pragma unroll
    for (int g = 0; g < 3; g++)
#pragma unroll
        for (int i = 0; i < 4; i++)
            wv[g][i] = *(const ulonglong2*)
                &w_hh[(size_t)(g * HH + j) * HH + kh * 512 + i * 128 + lane * 4];

    // Gate-math thread mapping: tid<256 -> (neuron gn, batch gb)
    const int gn = tid >> 5;            // valid when tid<256 (gn==warp then)
    const int gb = lane;
    float br = 0.f, bz = 0.f, bn = 0.f;
    if (tid < 256) {
        br = b_hh[0 * HH + j0 + gn];
        bz = b_hh[1 * HH + j0 + gn];
        bn = b_hh[2 * HH + j0 + gn];
    }

#pragma unroll 1
    for (int t = 0; t < TT; t++) {
        const float* cur = (t & 1) ? hb : ha;
        float*       nxt = (t & 1) ? ha : hb;

        // Prefetch gx for this step's gate math (DRAM latency hidden under dot)
        float xr = 0.f, xz = 0.f, xn = 0.f;
        if (tid < 256) {
            size_t gbase = ((size_t)gb * TT + t) * G3 + (j0 + gn);
            xr = __ldg(&gx[gbase]);
            xz = __ldg(&gx[gbase + HH]);
            xn = __ldg(&gx[gbase + 2 * HH]);
        }

        // Stage full h into smem (L2 -> smem), 16 iterations of float4
#pragma unroll
        for (int it = 0; it < (BB * HH / 4) / SCAN_THREADS; it++) {
            int idx = it * SCAN_THREADS + tid;
            float4 v = __ldcg((const float4*)cur + idx);
            ((float4*)sh_h)[idx] = v;
        }
        __syncthreads();

        // Dot products: 8 chunks of 4 batches
#pragma unroll 1
        for (int bc = 0; bc < 8; bc++) {
            unsigned long long acc[12];
#pragma unroll
            for (int v = 0; v < 12; v++) acc[v] = 0ULL;

#pragma unroll
            for (int i = 0; i < 4; i++) {
                ulonglong2 h2[4];
#pragma unroll
                for (int bb = 0; bb < 4; bb++)
                    h2[bb] = *(const ulonglong2*)
                        &sh_h[(bc * 4 + bb) * HH + kh * 512 + i * 128 + lane * 4];
#pragma unroll
                for (int bb = 0; bb < 4; bb++) {
#pragma unroll
                    for (int g = 0; g < 3; g++) {
                        fma2(acc[g * 4 + bb], h2[bb].x, wv[g][i].x);
                        fma2(acc[g * 4 + bb], h2[bb].y, wv[g][i].y);
                    }
                }
            }

            float s[12];
#pragma unroll
            for (int v = 0; v < 12; v++) {
                float2 f = unpack2(acc[v]);
                s[v] = f.x + f.y;
            }
#pragma unroll
            for (int off = 16; off > 0; off >>= 1) {
#pragma unroll
                for (int v = 0; v < 12; v++)
                    s[v] += __shfl_xor_sync(0xffffffffu, s[v], off);
            }
            if (lane == 0) {
#pragma unroll
                for (int v = 0; v < 12; v++) {
                    int g = v >> 2, bb = v & 3;
                    sh_sum[((kh * 3 + g) * 8 + nw) * 32 + bc * 4 + bb] = s[v];
                }
            }
        }
        __syncthreads();

        // Gate math: 256 threads = 8 neurons x 32 batches
        if (tid < 256) {
            float sr = sh_sum[((0 * 3 + 0) * 8 + gn) * 32 + gb]
                     + sh_sum[((1 * 3 + 0) * 8 + gn) * 32 + gb];
            float sz = sh_sum[((0 * 3 + 1) * 8 + gn) * 32 + gb]
                     + sh_sum[((1 * 3 + 1) * 8 + gn) * 32 + gb];
            float sn = sh_sum[((0 * 3 + 2) * 8 + gn) * 32 + gb]
                     + sh_sum[((1 * 3 + 2) * 8 + gn) * 32 + gb];
            float r  = 1.f / (1.f + __expf(-(xr + sr + br)));
            float z  = 1.f / (1.f + __expf(-(xz + sz + bz)));
            float nn = tanhf(xn + r * (sn + bn));
            float hold = sh_h[gb * HH + j0 + gn];
            float hnew = (1.f - z) * nn + z * hold;
            __stcg(&nxt[gb * HH + j0 + gn], hnew);
            if (writeOut) out[((size_t)gb * TT + t) * HH + j0 + gn] = hnew;
        }

        // Grid barrier: release h writes, arrive, spin, acquire
        __threadfence();
        __syncthreads();
        if (tid == 0) {
            atomicAdd(&g_bar, 1u);
            unsigned target = nCta * (unsigned)(t + 1);
            while (*((volatile unsigned*)&g_bar) < target) { }
            __threadfence();
        }
        __syncthreads();
    }
}

// ---------------------------------------------------------------------------
// Final FC: logits = sigmoid(h_last1 @ fc_w^T + fc_b). One warp per output.
// ---------------------------------------------------------------------------
__global__ __launch_bounds__(256) void fc_kernel(
    const float* __restrict__ h, const float* __restrict__ w,
    const float* __restrict__ bias, float* __restrict__ outp)
{
    int gw   = (int)((blockIdx.x * blockDim.x + threadIdx.x) >> 5);
    int lane = threadIdx.x & 31;
    if (gw >= BB * DOUT) return;
    int m = gw >> 8;
    int o = gw & 255;
    float acc = 0.f;
#pragma unroll
    for (int i = 0; i < 8; i++) {
        float4 hv = *(const float4*)&h[m * HH + i * 128 + lane * 4];
        float4 wv = *(const float4*)&w[o * HH + i * 128 + lane * 4];
        acc += hv.x * wv.x + hv.y * wv.y + hv.z * wv.z + hv.w * wv.w;
    }
#pragma unroll
    for (int off = 16; off > 0; off >>= 1)
        acc += __shfl_xor_sync(0xffffffffu, acc, off);
    if (lane == 0)
        outp[m * DOUT + o] = 1.f / (1.f + __expf(-(acc + bias[o])));
}

// ---------------------------------------------------------------------------
// Orchestration
// ---------------------------------------------------------------------------
extern "C" void kernel_launch(void* const* d_in, const int* in_sizes, int n_in,
                              void* d_out, int out_size)
{
    const float* input = (const float*)d_in[0];
    const float* w_ih0 = (const float*)d_in[1];
    const float* w_hh0 = (const float*)d_in[2];
    const float* b_ih0 = (const float*)d_in[3];
    const float* b_hh0 = (const float*)d_in[4];
    const float* w_ih1 = (const float*)d_in[5];
    const float* w_hh1 = (const float*)d_in[6];
    const float* b_ih1 = (const float*)d_in[7];
    const float* b_hh1 = (const float*)d_in[8];
    const float* fc_w  = (const float*)d_in[9];
    const float* fc_b  = (const float*)d_in[10];
    float* outp = (float*)d_out;

    float *gx, *out0, *ha, *hb;
    unsigned* bar;
    cudaGetSymbolAddress((void**)&gx,   g_gx);
    cudaGetSymbolAddress((void**)&out0, g_out0);
    cudaGetSymbolAddress((void**)&ha,   g_ha);
    cudaGetSymbolAddress((void**)&hb,   g_hb);
    cudaGetSymbolAddress((void**)&bar,  g_bar);

    // Allow 134KB dynamic smem for the scan kernel (idempotent; non-stream API)
    static int smem_set = 0;
    if (!smem_set) {
        cudaFuncSetAttribute(gru_scan_kernel,
                             cudaFuncAttributeMaxDynamicSharedMemorySize,
                             SMEM_FLOATS * (int)sizeof(float));
        smem_set = 1;
    }
    const int smem_bytes = SMEM_FLOATS * (int)sizeof(float);

    dim3 ggrid(G3 / 128, MTOT / 128);   // 24 x 128

    // Layer 0 input projection
    gemm_bias_kernel<<<ggrid, 256>>>(input, w_ih0, b_ih0, gx, MTOT, G3, DIN);

    // Layer 0 scan
    cudaMemsetAsync(ha, 0, BB * HH * sizeof(float));
    cudaMemsetAsync(bar, 0, sizeof(unsigned));
    gru_scan_kernel<<<128, SCAN_THREADS, smem_bytes>>>(gx, w_hh0, b_hh0, ha, hb, out0, 1);
    cudaMemcpyAsync(outp + BB * DOUT, ha, BB * HH * sizeof(float),
                    cudaMemcpyDeviceToDevice);

    // Layer 1 input projection
    gemm_bias_kernel<<<ggrid, 256>>>(out0, w_ih1, b_ih1, gx, MTOT, G3, HH);

    // Layer 1 scan
    cudaMemsetAsync(ha, 0, BB * HH * sizeof(float));
    cudaMemsetAsync(bar, 0, sizeof(unsigned));
    gru_scan_kernel<<<128, SCAN_THREADS, smem_bytes>>>(gx, w_hh1, b_hh1, ha, hb, nullptr, 0);
    cudaMemcpyAsync(outp + BB * DOUT + BB * HH, ha, BB * HH * sizeof(float),
                    cudaMemcpyDeviceToDevice);

    // Final FC
    fc_kernel<<<(BB * DOUT * 32) / 256, 256>>>(ha, fc_w, fc_b, outp);
}

// round 4
// speedup vs baseline: 5.3069x; 1.0013x over previous
#include <cuda_runtime.h>
#include <cstddef>

// Problem constants
#define BB   32
#define TT   512
#define DIN  256
#define HH   1024
#define G3   3072            // 3*H
#define DOUT 256
#define MTOT (BB * TT)       // 16384

// ---------------------------------------------------------------------------
// Static device scratch
// ---------------------------------------------------------------------------
__device__ float    g_gx[(size_t)MTOT * G3];   // reused for gx0 then gx1
__device__ float    g_out0[(size_t)MTOT * HH]; // layer-0 outputs
__device__ float    g_ha[BB * HH];
__device__ float    g_hb[BB * HH];
__device__ unsigned g_bar;

// ---------------------------------------------------------------------------
// Packed fp32x2 helpers
// ---------------------------------------------------------------------------
__device__ __forceinline__ unsigned long long pack_dup(float a) {
    unsigned long long r;
    asm("mov.b64 %0, {%1, %1};" : "=l"(r) : "f"(a));
    return r;
}
__device__ __forceinline__ void fma2(unsigned long long& c,
                                     unsigned long long a,
                                     unsigned long long b) {
    asm("fma.rn.f32x2 %0, %1, %2, %0;" : "+l"(c) : "l"(a), "l"(b));
}
__device__ __forceinline__ float2 unpack2(unsigned long long v) {
    float2 f;
    asm("mov.b64 {%0, %1}, %2;" : "=f"(f.x), "=f"(f.y) : "l"(v));
    return f;
}

// ---------------------------------------------------------------------------
// GEMM: C[M,N] = A[M,K] @ W[N,K]^T + bias[N]   (unchanged from R1 — ~1 ms total)
// ---------------------------------------------------------------------------
__global__ __launch_bounds__(256) void gemm_bias_kernel(
    const float* __restrict__ A, const float* __restrict__ W,
    const float* __restrict__ bias, float* __restrict__ C,
    int M, int N, int K)
{
    __shared__ __align__(16) float As[16][128];
    __shared__ __align__(16) float Ws[16][128];

    const int tid = threadIdx.x;
    const int m0 = blockIdx.y * 128;
    const int n0 = blockIdx.x * 128;
    const int tx = tid & 15;
    const int ty = tid >> 4;

    unsigned long long acc[8][4];
#pragma unroll
    for (int i = 0; i < 8; i++)
#pragma unroll
        for (int j = 0; j < 4; j++) acc[i][j] = 0ULL;

    const int lrow = tid >> 2;
    const int lc4  = tid & 3;

    for (int k0 = 0; k0 < K; k0 += 16) {
#pragma unroll
        for (int r = 0; r < 2; r++) {
            int row = lrow + r * 64;
            float4 va = *(const float4*)&A[(size_t)(m0 + row) * K + k0 + lc4 * 4];
            As[lc4 * 4 + 0][row] = va.x; As[lc4 * 4 + 1][row] = va.y;
            As[lc4 * 4 + 2][row] = va.z; As[lc4 * 4 + 3][row] = va.w;
            float4 vw = *(const float4*)&W[(size_t)(n0 + row) * K + k0 + lc4 * 4];
            Ws[lc4 * 4 + 0][row] = vw.x; Ws[lc4 * 4 + 1][row] = vw.y;
            Ws[lc4 * 4 + 2][row] = vw.z; Ws[lc4 * 4 + 3][row] = vw.w;
        }
        __syncthreads();
#pragma unroll
        for (int k = 0; k < 16; k++) {
            float4 a0 = *(const float4*)&As[k][ty * 8];
            float4 a1 = *(const float4*)&As[k][ty * 8 + 4];
            ulonglong2 b0 = *(const ulonglong2*)&Ws[k][tx * 8];
            ulonglong2 b1 = *(const ulonglong2*)&Ws[k][tx * 8 + 4];
            unsigned long long bp[4] = {b0.x, b0.y, b1.x, b1.y};
            float av[8] = {a0.x, a0.y, a0.z, a0.w, a1.x, a1.y, a1.z, a1.w};
#pragma unroll
            for (int i = 0; i < 8; i++) {
                unsigned long long ap = pack_dup(av[i]);
#pragma unroll
                for (int j = 0; j < 4; j++) fma2(acc[i][j], ap, bp[j]);
            }
        }
        __syncthreads();
    }

#pragma unroll
    for (int i = 0; i < 8; i++) {
        int m = m0 + ty * 8 + i;
#pragma unroll
        for (int j = 0; j < 4; j++) {
            float2 v = unpack2(acc[i][j]);
            int n = n0 + tx * 8 + j * 2;
            C[(size_t)m * N + n]     = v.x + bias[n];
            C[(size_t)m * N + n + 1] = v.y + bias[n + 1];
        }
    }
}

// ---------------------------------------------------------------------------
// GRU scan v2: 128 CTAs x 512 threads, persistent, grid barrier per step.
//   smem: full h state (32x1024 f32 = 128KB) staged once per step,
//         plus partial-sum buffer [2 khalf][3 gate][8 neuron][32 batch].
//   Warp w: neuron nw = w>>1 (j = blockIdx*8+nw), k-half kh = w&1.
//   Weights (3 gates x 512 k) register-stationary: 12 ulonglong2 = 48 regs.
//   Inner loop: 4 batches in flight -> 12 independent fma2 chains (ILP),
//   all h reads from smem (LDS, 29cyc), gx prefetched at step start.
// ---------------------------------------------------------------------------
#define SCAN_THREADS 512
#define SUM_OFF (BB * HH)                       // floats
#define SMEM_FLOATS (BB * HH + 2 * 3 * 8 * 32)  // 131072 + 6144 bytes

__global__ __launch_bounds__(SCAN_THREADS) void gru_scan_kernel(
    const float* __restrict__ gx, const float* __restrict__ w_hh,
    const float* __restrict__ b_hh, float* __restrict__ ha,
    float* __restrict__ hb, float* __restrict__ out, int writeOut)
{
    extern __shared__ __align__(16) float sh[];
    float* sh_h   = sh;            // [BB][HH]
    float* sh_sum = sh + SUM_OFF;  // [2][3][8][32]

    const int tid  = threadIdx.x;
    const int warp = tid >> 5;
    const int lane = tid & 31;
    const int nw   = warp >> 1;          // neuron within CTA (0..7)
    const int kh   = warp & 1;           // k-half
    const int j0   = blockIdx.x * 8;
    const int j    = j0 + nw;
    const unsigned nCta = gridDim.x;

    // Register-stationary weights: w_hh[(g*HH+j)*HH + kh*512 + i*128 + lane*4]
    ulonglong2 wv[3][4];
#pragma unroll
    for (int g = 0; g < 3; g++)
#pragma unroll
        for (int i = 0; i < 4; i++)
            wv[g][i] = *(const ulonglong2*)
                &w_hh[(size_t)(g * HH + j) * HH + kh * 512 + i * 128 + lane * 4];

    // Gate-math thread mapping: tid<256 -> (neuron gn, batch gb)
    const int gn = tid >> 5;            // valid when tid<256 (gn==warp then)
    const int gb = lane;
    float br = 0.f, bz = 0.f, bn = 0.f;
    if (tid < 256) {
        br = b_hh[0 * HH + j0 + gn];
        bz = b_hh[1 * HH + j0 + gn];
        bn = b_hh[2 * HH + j0 + gn];
    }

#pragma unroll 1
    for (int t = 0; t < TT; t++) {
        const float* cur = (t & 1) ? hb : ha;
        float*       nxt = (t & 1) ? ha : hb;

        // Prefetch gx for this step's gate math (DRAM latency hidden under dot)
        float xr = 0.f, xz = 0.f, xn = 0.f;
        if (tid < 256) {
            size_t gbase = ((size_t)gb * TT + t) * G3 + (j0 + gn);
            xr = __ldg(&gx[gbase]);
            xz = __ldg(&gx[gbase + HH]);
            xn = __ldg(&gx[gbase + 2 * HH]);
        }

        // Stage full h into smem (L2 -> smem), 16 iterations of float4
#pragma unroll
        for (int it = 0; it < (BB * HH / 4) / SCAN_THREADS; it++) {
            int idx = it * SCAN_THREADS + tid;
            float4 v = __ldcg((const float4*)cur + idx);
            ((float4*)sh_h)[idx] = v;
        }
        __syncthreads();

        // Dot products: 8 chunks of 4 batches
#pragma unroll 1
        for (int bc = 0; bc < 8; bc++) {
            unsigned long long acc[12];
#pragma unroll
            for (int v = 0; v < 12; v++) acc[v] = 0ULL;

#pragma unroll
            for (int i = 0; i < 4; i++) {
                ulonglong2 h2[4];
#pragma unroll
                for (int bb = 0; bb < 4; bb++)
                    h2[bb] = *(const ulonglong2*)
                        &sh_h[(bc * 4 + bb) * HH + kh * 512 + i * 128 + lane * 4];
#pragma unroll
                for (int bb = 0; bb < 4; bb++) {
#pragma unroll
                    for (int g = 0; g < 3; g++) {
                        fma2(acc[g * 4 + bb], h2[bb].x, wv[g][i].x);
                        fma2(acc[g * 4 + bb], h2[bb].y, wv[g][i].y);
                    }
                }
            }

            float s[12];
#pragma unroll
            for (int v = 0; v < 12; v++) {
                float2 f = unpack2(acc[v]);
                s[v] = f.x + f.y;
            }
#pragma unroll
            for (int off = 16; off > 0; off >>= 1) {
#pragma unroll
                for (int v = 0; v < 12; v++)
                    s[v] += __shfl_xor_sync(0xffffffffu, s[v], off);
            }
            if (lane == 0) {
#pragma unroll
                for (int v = 0; v < 12; v++) {
                    int g = v >> 2, bb = v & 3;
                    sh_sum[((kh * 3 + g) * 8 + nw) * 32 + bc * 4 + bb] = s[v];
                }
            }
        }
        __syncthreads();

        // Gate math: 256 threads = 8 neurons x 32 batches
        if (tid < 256) {
            float sr = sh_sum[((0 * 3 + 0) * 8 + gn) * 32 + gb]
                     + sh_sum[((1 * 3 + 0) * 8 + gn) * 32 + gb];
            float sz = sh_sum[((0 * 3 + 1) * 8 + gn) * 32 + gb]
                     + sh_sum[((1 * 3 + 1) * 8 + gn) * 32 + gb];
            float sn = sh_sum[((0 * 3 + 2) * 8 + gn) * 32 + gb]
                     + sh_sum[((1 * 3 + 2) * 8 + gn) * 32 + gb];
            float r  = 1.f / (1.f + __expf(-(xr + sr + br)));
            float z  = 1.f / (1.f + __expf(-(xz + sz + bz)));
            float nn = tanhf(xn + r * (sn + bn));
            float hold = sh_h[gb * HH + j0 + gn];
            float hnew = (1.f - z) * nn + z * hold;
            __stcg(&nxt[gb * HH + j0 + gn], hnew);
            if (writeOut) out[((size_t)gb * TT + t) * HH + j0 + gn] = hnew;
        }

        // Grid barrier: release h writes, arrive, spin, acquire
        __threadfence();
        __syncthreads();
        if (tid == 0) {
            atomicAdd(&g_bar, 1u);
            unsigned target = nCta * (unsigned)(t + 1);
            while (*((volatile unsigned*)&g_bar) < target) { }
            __threadfence();
        }
        __syncthreads();
    }
}

// ---------------------------------------------------------------------------
// Final FC: logits = sigmoid(h_last1 @ fc_w^T + fc_b). One warp per output.
// ---------------------------------------------------------------------------
__global__ __launch_bounds__(256) void fc_kernel(
    const float* __restrict__ h, const float* __restrict__ w,
    const float* __restrict__ bias, float* __restrict__ outp)
{
    int gw   = (int)((blockIdx.x * blockDim.x + threadIdx.x) >> 5);
    int lane = threadIdx.x & 31;
    if (gw >= BB * DOUT) return;
    int m = gw >> 8;
    int o = gw & 255;
    float acc = 0.f;
#pragma unroll
    for (int i = 0; i < 8; i++) {
        float4 hv = *(const float4*)&h[m * HH + i * 128 + lane * 4];
        float4 wv = *(const float4*)&w[o * HH + i * 128 + lane * 4];
        acc += hv.x * wv.x + hv.y * wv.y + hv.z * wv.z + hv.w * wv.w;
    }
#pragma unroll
    for (int off = 16; off > 0; off >>= 1)
        acc += __shfl_xor_sync(0xffffffffu, acc, off);
    if (lane == 0)
        outp[m * DOUT + o] = 1.f / (1.f + __expf(-(acc + bias[o])));
}

// ---------------------------------------------------------------------------
// Orchestration
// ---------------------------------------------------------------------------
extern "C" void kernel_launch(void* const* d_in, const int* in_sizes, int n_in,
                              void* d_out, int out_size)
{
    const float* input = (const float*)d_in[0];
    const float* w_ih0 = (const float*)d_in[1];
    const float* w_hh0 = (const float*)d_in[2];
    const float* b_ih0 = (const float*)d_in[3];
    const float* b_hh0 = (const float*)d_in[4];
    const float* w_ih1 = (const float*)d_in[5];
    const float* w_hh1 = (const float*)d_in[6];
    const float* b_ih1 = (const float*)d_in[7];
    const float* b_hh1 = (const float*)d_in[8];
    const float* fc_w  = (const float*)d_in[9];
    const float* fc_b  = (const float*)d_in[10];
    float* outp = (float*)d_out;

    float *gx, *out0, *ha, *hb;
    unsigned* bar;
    cudaGetSymbolAddress((void**)&gx,   g_gx);
    cudaGetSymbolAddress((void**)&out0, g_out0);
    cudaGetSymbolAddress((void**)&ha,   g_ha);
    cudaGetSymbolAddress((void**)&hb,   g_hb);
    cudaGetSymbolAddress((void**)&bar,  g_bar);

    // Allow 134KB dynamic smem for the scan kernel (idempotent; non-stream API)
    static int smem_set = 0;
    if (!smem_set) {
        cudaFuncSetAttribute(gru_scan_kernel,
                             cudaFuncAttributeMaxDynamicSharedMemorySize,
                             SMEM_FLOATS * (int)sizeof(float));
        smem_set = 1;
    }
    const int smem_bytes = SMEM_FLOATS * (int)sizeof(float);

    dim3 ggrid(G3 / 128, MTOT / 128);   // 24 x 128

    // Layer 0 input projection
    gemm_bias_kernel<<<ggrid, 256>>>(input, w_ih0, b_ih0, gx, MTOT, G3, DIN);

    // Layer 0 scan
    cudaMemsetAsync(ha, 0, BB * HH * sizeof(float));
    cudaMemsetAsync(bar, 0, sizeof(unsigned));
    gru_scan_kernel<<<128, SCAN_THREADS, smem_bytes>>>(gx, w_hh0, b_hh0, ha, hb, out0, 1);
    cudaMemcpyAsync(outp + BB * DOUT, ha, BB * HH * sizeof(float),
                    cudaMemcpyDeviceToDevice);

    // Layer 1 input projection
    gemm_bias_kernel<<<ggrid, 256>>>(out0, w_ih1, b_ih1, gx, MTOT, G3, HH);

    // Layer 1 scan
    cudaMemsetAsync(ha, 0, BB * HH * sizeof(float));
    cudaMemsetAsync(bar, 0, sizeof(unsigned));
    gru_scan_kernel<<<128, SCAN_THREADS, smem_bytes>>>(gx, w_hh1, b_hh1, ha, hb, nullptr, 0);
    cudaMemcpyAsync(outp + BB * DOUT + BB * HH, ha, BB * HH * sizeof(float),
                    cudaMemcpyDeviceToDevice);

    // Final FC
    fc_kernel<<<(BB * DOUT * 32) / 256, 256>>>(ha, fc_w, fc_b, outp);
}

// round 6
// speedup vs baseline: 11.6328x; 2.1920x over previous
#include <cuda_runtime.h>
#include <cuda_fp16.h>
#include <cstdint>
#include <cstddef>

#define BB 32
#define TT 512
#define DIN 256
#define HH 1024
#define G3 3072
#define DOUT 256
#define MTOT (BB*TT)

// ---- static device scratch ----
__device__ float    g_gx[(size_t)MTOT*G3];
__device__ float    g_out0[(size_t)MTOT*HH];
__device__ float    g_ha[BB*HH];
__device__ float    g_hb[BB*HH];
__device__ uint8_t  g_pHi[2][BB*HH*2];   // h hi halves, A-fragment layout, ping-pong
__device__ uint8_t  g_pLo[2][BB*HH*2];   // h lo halves
__device__ unsigned g_bar;

// ---- f32x2 helpers (SIMT GEMM) ----
__device__ __forceinline__ unsigned long long pack_dup(float a){
    unsigned long long r; asm("mov.b64 %0, {%1, %1};":"=l"(r):"f"(a)); return r; }
__device__ __forceinline__ void fma2(unsigned long long& c, unsigned long long a, unsigned long long b){
    asm("fma.rn.f32x2 %0, %1, %2, %0;":"+l"(c):"l"(a),"l"(b)); }
__device__ __forceinline__ float2 unpack2(unsigned long long v){
    float2 f; asm("mov.b64 {%0, %1}, %2;":"=f"(f.x),"=f"(f.y):"l"(v)); return f; }

// ---- mma.sync helpers ----
__device__ __forceinline__ void mma16816(float* c, const uint32_t* a, const uint32_t* b){
    asm volatile("mma.sync.aligned.m16n8k16.row.col.f32.f16.f16.f32 "
        "{%0,%1,%2,%3}, {%4,%5,%6,%7}, {%8,%9}, {%0,%1,%2,%3};"
        : "+f"(c[0]),"+f"(c[1]),"+f"(c[2]),"+f"(c[3])
        : "r"(a[0]),"r"(a[1]),"r"(a[2]),"r"(a[3]),"r"(b[0]),"r"(b[1]));
}
__device__ __forceinline__ void split_h(float x, __half& hi, __half& lo){
    hi = __float2half_rn(x);
    lo = __float2half_rn(x - __half2float(hi));
}
__device__ __forceinline__ uint32_t pack_h2(__half a, __half b){
    __half2 v = __halves2half2(a, b);
    return *(uint32_t*)&v;
}
__device__ __forceinline__ void st_u16_cg(uint8_t* p, unsigned short v){
    asm volatile("st.global.cg.u16 [%0], %1;" :: "l"(p), "h"(v) : "memory");
}
__device__ __forceinline__ uint4 ld_u128_cg(const uint8_t* p){
    uint4 v;
    asm volatile("ld.global.cg.v4.u32 {%0,%1,%2,%3}, [%4];"
                 : "=r"(v.x),"=r"(v.y),"=r"(v.z),"=r"(v.w) : "l"(p));
    return v;
}

// ---- SIMT GEMM (unchanged) ----
__global__ __launch_bounds__(256) void gemm_bias_kernel(
    const float* __restrict__ A, const float* __restrict__ W,
    const float* __restrict__ bias, float* __restrict__ C, int M, int N, int K)
{
    __shared__ __align__(16) float As[16][128];
    __shared__ __align__(16) float Ws[16][128];
    const int tid=threadIdx.x, m0=blockIdx.y*128, n0=blockIdx.x*128, tx=tid&15, ty=tid>>4;
    unsigned long long acc[8][4];
#pragma unroll
    for(int i=0;i<8;i++)
#pragma unroll
        for(int j=0;j<4;j++) acc[i][j]=0ULL;
    const int lrow=tid>>2, lc4=tid&3;
    for(int k0=0;k0<K;k0+=16){
#pragma unroll
        for(int r=0;r<2;r++){
            int row=lrow+r*64;
            float4 va=*(const float4*)&A[(size_t)(m0+row)*K+k0+lc4*4];
            As[lc4*4+0][row]=va.x; As[lc4*4+1][row]=va.y; As[lc4*4+2][row]=va.z; As[lc4*4+3][row]=va.w;
            float4 vw=*(const float4*)&W[(size_t)(n0+row)*K+k0+lc4*4];
            Ws[lc4*4+0][row]=vw.x; Ws[lc4*4+1][row]=vw.y; Ws[lc4*4+2][row]=vw.z; Ws[lc4*4+3][row]=vw.w;
        }
        __syncthreads();
#pragma unroll
        for(int k=0;k<16;k++){
            float4 a0=*(const float4*)&As[k][ty*8];
            float4 a1=*(const float4*)&As[k][ty*8+4];
            ulonglong2 b0=*(const ulonglong2*)&Ws[k][tx*8];
            ulonglong2 b1=*(const ulonglong2*)&Ws[k][tx*8+4];
            unsigned long long bp[4]={b0.x,b0.y,b1.x,b1.y};
            float av[8]={a0.x,a0.y,a0.z,a0.w,a1.x,a1.y,a1.z,a1.w};
#pragma unroll
            for(int i=0;i<8;i++){
                unsigned long long ap=pack_dup(av[i]);
#pragma unroll
                for(int j=0;j<4;j++) fma2(acc[i][j],ap,bp[j]);
            }
        }
        __syncthreads();
    }
#pragma unroll
    for(int i=0;i<8;i++){
        int m=m0+ty*8+i;
#pragma unroll
        for(int j=0;j<4;j++){
            float2 v=unpack2(acc[i][j]);
            int n=n0+tx*8+j*2;
            C[(size_t)m*N+n]=v.x+bias[n];
            C[(size_t)m*N+n+1]=v.y+bias[n+1];
        }
    }
}

// ---------------------------------------------------------------------------
// HMMA GRU scan: 128 CTAs x 512 thr. CTA owns 8 neurons (24 gate rows).
// pre[32x24] = h[32x1024] . W[24x1024]^T via fp16 hi/lo 3-term mma.sync.
// Warp w owns K-slice [w*64, w*64+64); W fragments register-stationary.
// h stored in global in A-fragment order (hi/lo pair buffers, ping-pong):
// readers do coalesced LDG.128, writers scatter 2B stores.
// ---------------------------------------------------------------------------
__global__ __launch_bounds__(512) void gru_scan_hmma(
    const float* __restrict__ gx, const float* __restrict__ w_hh,
    const float* __restrict__ b_hh, float* __restrict__ out, int writeOut)
{
    __shared__ float red[16*768];   // 48KB: [warp][mt*3+nt][r*8+c] partials

    const int tid=threadIdx.x, warp=tid>>5, lane=tid&31, j0=blockIdx.x*8;
    const unsigned nCta=gridDim.x;
    const int grp=lane>>2, tig=lane&3;

    // ---- Build B fragments once: Bh/Bl[nt][kt][2] ----
    uint32_t Bh[3][4][2], Bl[3][4][2];
#pragma unroll
    for(int nt=0; nt<3; nt++){
        const float* wr = w_hh + (size_t)(nt*HH + j0 + grp)*HH;  // gate nt, neuron grp
#pragma unroll
        for(int kt=0; kt<4; kt++){
            int k0 = warp*64 + kt*16 + tig*2;
            float f0=wr[k0], f1=wr[k0+1], f2=wr[k0+8], f3=wr[k0+9];
            __half h0,l0,h1,l1,h2,l2,h3,l3;
            split_h(f0,h0,l0); split_h(f1,h1,l1); split_h(f2,h2,l2); split_h(f3,h3,l3);
            Bh[nt][kt][0]=pack_h2(h0,h1); Bh[nt][kt][1]=pack_h2(h2,h3);
            Bl[nt][kt][0]=pack_h2(l0,l1); Bl[nt][kt][1]=pack_h2(l2,l3);
        }
    }

    // Gate-thread mapping (tid<256): batch b, neuron nr
    const int gb=tid>>3, gnr=tid&7;
    float br_=0.f,bz_=0.f,bn_=0.f;
    size_t woff=0;
    if(tid<256){
        br_=b_hh[j0+gnr]; bz_=b_hh[HH+j0+gnr]; bn_=b_hh[2*HH+j0+gnr];
        int j=j0+gnr, gkt=j>>4, c=j&15, mt=gb>>4, r=gb&15;
        int ln=(r&7)*4+((c>>1)&3), q=((r>>3)&1)+2*((c>>3)&1);
        woff=(((size_t)(gkt*2+mt))<<9) + ln*16 + q*4 + (c&1)*2;
    }

#pragma unroll 1
    for(int t=0; t<TT; t++){
        const uint8_t* pHiC=g_pHi[t&1];
        const uint8_t* pLoC=g_pLo[t&1];
        uint8_t* pHiN=g_pHi[(t+1)&1];
        uint8_t* pLoN=g_pLo[(t+1)&1];
        const float* cur32=(t&1)?g_hb:g_ha;
        float* nxt32=(t&1)?g_ha:g_hb;

        // Prefetch gx + h_old for gate threads
        float xr=0.f,xz=0.f,xn=0.f,hold=0.f;
        if(tid<256){
            size_t gbase=((size_t)gb*TT+t)*G3+(j0+gnr);
            xr=__ldg(&gx[gbase]); xz=__ldg(&gx[gbase+HH]); xn=__ldg(&gx[gbase+2*HH]);
            hold=__ldcg(&cur32[gb*HH+j0+gnr]);
        }

        // ---- MMA: per mt, load A frags then 36 HMMA ----
#pragma unroll
        for(int mt=0; mt<2; mt++){
            uint4 Ah[4], Al[4];
#pragma unroll
            for(int kt=0; kt<4; kt++){
                int gkt=warp*4+kt;
                size_t off=(((size_t)(gkt*2+mt))<<9)+lane*16;
                Ah[kt]=ld_u128_cg(pHiC+off);
                Al[kt]=ld_u128_cg(pLoC+off);
            }
            float C[3][4];
#pragma unroll
            for(int nt=0;nt<3;nt++)
#pragma unroll
                for(int i=0;i<4;i++) C[nt][i]=0.f;
#pragma unroll
            for(int nt=0; nt<3; nt++){
#pragma unroll
                for(int kt=0; kt<4; kt++){
                    mma16816(C[nt], (const uint32_t*)&Ah[kt], Bh[nt][kt]);
                    mma16816(C[nt], (const uint32_t*)&Al[kt], Bh[nt][kt]);
                    mma16816(C[nt], (const uint32_t*)&Ah[kt], Bl[nt][kt]);
                }
            }
            // store partials: c0:(grp, tig*2) c1:+1 c2:(grp+8,..) c3
#pragma unroll
            for(int nt=0; nt<3; nt++){
                float* rb=&red[warp*768 + (mt*3+nt)*128];
                int p0=grp*8+tig*2;
                rb[p0]=C[nt][0]; rb[p0+1]=C[nt][1];
                rb[p0+64]=C[nt][2]; rb[p0+65]=C[nt][3];
            }
        }
        __syncthreads();

        // ---- Reduce 16 warps + gate math ----
        if(tid<256){
            int mt=gb>>4, r=gb&15;
            float pr=0.f,pz=0.f,pn=0.f;
#pragma unroll
            for(int w=0; w<16; w++){
                int base=w*768 + mt*384 + r*8 + gnr;
                pr+=red[base];
                pz+=red[base+128];
                pn+=red[base+256];
            }
            float rr=1.f/(1.f+__expf(-(xr+pr+br_)));
            float zz=1.f/(1.f+__expf(-(xz+pz+bz_)));
            float nn=tanhf(xn+rr*(pn+bn_));
            float hnew=(1.f-zz)*nn+zz*hold;
            // fp32 state (for hold + final output)
            __stcg(&nxt32[gb*HH+j0+gnr],hnew);
            // fp16 pair state in fragment layout
            __half hi,lo; split_h(hnew,hi,lo);
            st_u16_cg(pHiN+woff, *(unsigned short*)&hi);
            st_u16_cg(pLoN+woff, *(unsigned short*)&lo);
            if(writeOut) out[((size_t)gb*TT+t)*HH+j0+gnr]=hnew;
        }

        // ---- grid barrier ----
        __threadfence();
        __syncthreads();
        if(tid==0){
            atomicAdd(&g_bar,1u);
            unsigned target=nCta*(unsigned)(t+1);
            while(*((volatile unsigned*)&g_bar)<target){}
            __threadfence();
        }
        __syncthreads();
    }
}

// ---- FC ----
__global__ __launch_bounds__(256) void fc_kernel(
    const float* __restrict__ h, const float* __restrict__ w,
    const float* __restrict__ bias, float* __restrict__ outp)
{
    int gw=(int)((blockIdx.x*blockDim.x+threadIdx.x)>>5), lane=threadIdx.x&31;
    if(gw>=BB*DOUT) return;
    int m=gw>>8, o=gw&255;
    float acc=0.f;
#pragma unroll
    for(int i=0;i<8;i++){
        float4 hv=*(const float4*)&h[m*HH+i*128+lane*4];
        float4 wv=*(const float4*)&w[o*HH+i*128+lane*4];
        acc+=hv.x*wv.x+hv.y*wv.y+hv.z*wv.z+hv.w*wv.w;
    }
#pragma unroll
    for(int off=16;off>0;off>>=1) acc+=__shfl_xor_sync(0xffffffffu,acc,off);
    if(lane==0) outp[m*DOUT+o]=1.f/(1.f+__expf(-(acc+bias[o])));
}

extern "C" void kernel_launch(void* const* d_in, const int* in_sizes, int n_in,
                              void* d_out, int out_size)
{
    const float* input=(const float*)d_in[0];
    const float* w_ih0=(const float*)d_in[1];
    const float* w_hh0=(const float*)d_in[2];
    const float* b_ih0=(const float*)d_in[3];
    const float* b_hh0=(const float*)d_in[4];
    const float* w_ih1=(const float*)d_in[5];
    const float* w_hh1=(const float*)d_in[6];
    const float* b_ih1=(const float*)d_in[7];
    const float* b_hh1=(const float*)d_in[8];
    const float* fc_w=(const float*)d_in[9];
    const float* fc_b=(const float*)d_in[10];
    float* outp=(float*)d_out;

    float *gx,*out0,*ha; unsigned* bar; uint8_t *pHi,*pLo;
    cudaGetSymbolAddress((void**)&gx,g_gx);
    cudaGetSymbolAddress((void**)&out0,g_out0);
    cudaGetSymbolAddress((void**)&ha,g_ha);
    cudaGetSymbolAddress((void**)&bar,g_bar);
    cudaGetSymbolAddress((void**)&pHi,g_pHi);
    cudaGetSymbolAddress((void**)&pLo,g_pLo);

    dim3 ggrid(G3/128, MTOT/128);

    // Layer 0 input projection
    gemm_bias_kernel<<<ggrid,256>>>(input,w_ih0,b_ih0,gx,MTOT,G3,DIN);

    // Layer 0 scan (zero: fp32 ha, pair buf0, barrier)
    cudaMemsetAsync(ha,0,BB*HH*sizeof(float));
    cudaMemsetAsync(pHi,0,BB*HH*2);
    cudaMemsetAsync(pLo,0,BB*HH*2);
    cudaMemsetAsync(bar,0,sizeof(unsigned));
    gru_scan_hmma<<<128,512>>>(gx,w_hh0,b_hh0,out0,1);
    // TT even -> final h in g_ha
    cudaMemcpyAsync(outp+BB*DOUT,ha,BB*HH*sizeof(float),cudaMemcpyDeviceToDevice);

    // Layer 1 input projection
    gemm_bias_kernel<<<ggrid,256>>>(out0,w_ih1,b_ih1,gx,MTOT,G3,HH);

    // Layer 1 scan
    cudaMemsetAsync(ha,0,BB*HH*sizeof(float));
    cudaMemsetAsync(pHi,0,BB*HH*2);
    cudaMemsetAsync(pLo,0,BB*HH*2);
    cudaMemsetAsync(bar,0,sizeof(unsigned));
    gru_scan_hmma<<<128,512>>>(gx,w_hh1,b_hh1,nullptr,0);
    cudaMemcpyAsync(outp+BB*DOUT+BB*HH,ha,BB*HH*sizeof(float),cudaMemcpyDeviceToDevice);

    fc_kernel<<<(BB*DOUT*32)/256,256>>>(ha,fc_w,fc_b,outp);
}

// round 7
// speedup vs baseline: 15.0933x; 1.2975x over previous
#include <cuda_runtime.h>
#include <cuda_fp16.h>
#include <cstdint>
#include <cstddef>

#define BB 32
#define TT 512
#define DIN 256
#define HH 1024
#define G3 3072
#define DOUT 256
#define MTOT (BB*TT)

// ---- static device scratch ----
__device__ float    g_gx[(size_t)MTOT*G3];
__device__ float    g_out0[(size_t)MTOT*HH];
__device__ float    g_ha[BB*HH];
__device__ float    g_hb[BB*HH];
__device__ uint8_t  g_pHi[2][BB*HH*2];   // h hi halves, A-fragment layout, ping-pong
__device__ uint8_t  g_pLo[2][BB*HH*2];   // h lo halves
__device__ unsigned g_bar;

// ---- mma.sync helpers (fragment layouts verified by the passing scan) ----
__device__ __forceinline__ void mma16816(float* c, const uint32_t* a, const uint32_t* b){
    asm volatile("mma.sync.aligned.m16n8k16.row.col.f32.f16.f16.f32 "
        "{%0,%1,%2,%3}, {%4,%5,%6,%7}, {%8,%9}, {%0,%1,%2,%3};"
        : "+f"(c[0]),"+f"(c[1]),"+f"(c[2]),"+f"(c[3])
        : "r"(a[0]),"r"(a[1]),"r"(a[2]),"r"(a[3]),"r"(b[0]),"r"(b[1]));
}
__device__ __forceinline__ void split_h(float x, __half& hi, __half& lo){
    hi = __float2half_rn(x);
    lo = __float2half_rn(x - __half2float(hi));
}
__device__ __forceinline__ uint32_t pack_h2(__half a, __half b){
    __half2 v = __halves2half2(a, b);
    return *(uint32_t*)&v;
}
__device__ __forceinline__ void st_u16_cg(uint8_t* p, unsigned short v){
    asm volatile("st.global.cg.u16 [%0], %1;" :: "l"(p), "h"(v) : "memory");
}
__device__ __forceinline__ uint4 ld_u128_cg(const uint8_t* p){
    uint4 v;
    asm volatile("ld.global.cg.v4.u32 {%0,%1,%2,%3}, [%4];"
                 : "=r"(v.x),"=r"(v.y),"=r"(v.z),"=r"(v.w) : "l"(p));
    return v;
}
// split a float4 into 4 hi halfs + 4 lo halfs packed as uint2 each
__device__ __forceinline__ void split4_h(float4 v, uint2& hi, uint2& lo){
    __half h0,l0,h1,l1,h2,l2,h3,l3;
    split_h(v.x,h0,l0); split_h(v.y,h1,l1); split_h(v.z,h2,l2); split_h(v.w,h3,l3);
    hi.x = pack_h2(h0,h1); hi.y = pack_h2(h2,h3);
    lo.x = pack_h2(l0,l1); lo.y = pack_h2(l2,l3);
}

// ---------------------------------------------------------------------------
// HMMA GEMM: C[M,N] = A[M,K] @ W[N,K]^T + bias[N], fp16 hi/lo 3-term.
// 256 thr = 8 warps (2m x 4n), CTA tile 128x128, BK=32 (2 k-chunks of 16).
// smem pitch 40 halfs -> conflict-free fragment reads.
// ---------------------------------------------------------------------------
#define GPITCH 40
__global__ __launch_bounds__(256) void gemm_hmma(
    const float* __restrict__ A, const float* __restrict__ W,
    const float* __restrict__ bias, float* __restrict__ C, int M, int N, int K)
{
    __shared__ __half Ash[128*GPITCH], Asl[128*GPITCH];
    __shared__ __half Bsh[128*GPITCH], Bsl[128*GPITCH];

    const int tid=threadIdx.x, warp=tid>>5, lane=tid&31;
    const int grp=lane>>2, tig=lane&3;
    const int warpM=warp>>2, warpN=warp&3;
    const int m0=blockIdx.y*128, n0=blockIdx.x*128;

    float acc[4][4][4];
#pragma unroll
    for(int mt=0;mt<4;mt++)
#pragma unroll
        for(int nt=0;nt<4;nt++)
#pragma unroll
            for(int i=0;i<4;i++) acc[mt][nt][i]=0.f;

    for(int k0=0;k0<K;k0+=32){
        // ---- stage + split A and B tiles (128x32 fp32 each) ----
#pragma unroll
        for(int i=0;i<4;i++){
            int id=tid+i*256;            // 1024 float4 = 128 rows x 8
            int row=id>>3, k4=(id&7)*4;
            float4 va=__ldg((const float4*)&A[(size_t)(m0+row)*K+k0+k4]);
            uint2 hi,lo; split4_h(va,hi,lo);
            *(uint2*)&Ash[row*GPITCH+k4]=hi;
            *(uint2*)&Asl[row*GPITCH+k4]=lo;
            float4 vw=__ldg((const float4*)&W[(size_t)(n0+row)*K+k0+k4]);
            split4_h(vw,hi,lo);
            *(uint2*)&Bsh[row*GPITCH+k4]=hi;
            *(uint2*)&Bsl[row*GPITCH+k4]=lo;
        }
        __syncthreads();

#pragma unroll
        for(int kc=0;kc<2;kc++){
            const int ko=kc*16+tig*2;
            // B fragments for 4 n-tiles
            uint32_t bh[4][2], bl[4][2];
#pragma unroll
            for(int nt=0;nt<4;nt++){
                int r=warpN*32+nt*8+grp;
                bh[nt][0]=*(uint32_t*)&Bsh[r*GPITCH+ko];
                bh[nt][1]=*(uint32_t*)&Bsh[r*GPITCH+ko+8];
                bl[nt][0]=*(uint32_t*)&Bsl[r*GPITCH+ko];
                bl[nt][1]=*(uint32_t*)&Bsl[r*GPITCH+ko+8];
            }
#pragma unroll
            for(int mt=0;mt<4;mt++){
                int r=warpM*64+mt*16+grp;
                uint32_t ah[4], al[4];
                ah[0]=*(uint32_t*)&Ash[r*GPITCH+ko];
                ah[1]=*(uint32_t*)&Ash[(r+8)*GPITCH+ko];
                ah[2]=*(uint32_t*)&Ash[r*GPITCH+ko+8];
                ah[3]=*(uint32_t*)&Ash[(r+8)*GPITCH+ko+8];
                al[0]=*(uint32_t*)&Asl[r*GPITCH+ko];
                al[1]=*(uint32_t*)&Asl[(r+8)*GPITCH+ko];
                al[2]=*(uint32_t*)&Asl[r*GPITCH+ko+8];
                al[3]=*(uint32_t*)&Asl[(r+8)*GPITCH+ko+8];
#pragma unroll
                for(int nt=0;nt<4;nt++){
                    mma16816(acc[mt][nt], ah, bh[nt]);
                    mma16816(acc[mt][nt], al, bh[nt]);
                    mma16816(acc[mt][nt], ah, bl[nt]);
                }
            }
        }
        __syncthreads();
    }

    // ---- epilogue: add bias, store fp32 ----
#pragma unroll
    for(int mt=0;mt<4;mt++){
        int r=m0+warpM*64+mt*16+grp;
#pragma unroll
        for(int nt=0;nt<4;nt++){
            int c=n0+warpN*32+nt*8+tig*2;
            float b0=bias[c], b1=bias[c+1];
            float2 v0={acc[mt][nt][0]+b0, acc[mt][nt][1]+b1};
            float2 v1={acc[mt][nt][2]+b0, acc[mt][nt][3]+b1};
            *(float2*)&C[(size_t)r*N+c]=v0;
            *(float2*)&C[(size_t)(r+8)*N+c]=v1;
        }
    }
}

// ---------------------------------------------------------------------------
// HMMA GRU scan (unchanged from R5 — verified, 2.04us/step)
// ---------------------------------------------------------------------------
__global__ __launch_bounds__(512) void gru_scan_hmma(
    const float* __restrict__ gx, const float* __restrict__ w_hh,
    const float* __restrict__ b_hh, float* __restrict__ out, int writeOut)
{
    __shared__ float red[16*768];

    const int tid=threadIdx.x, warp=tid>>5, lane=tid&31, j0=blockIdx.x*8;
    const unsigned nCta=gridDim.x;
    const int grp=lane>>2, tig=lane&3;

    uint32_t Bh[3][4][2], Bl[3][4][2];
#pragma unroll
    for(int nt=0; nt<3; nt++){
        const float* wr = w_hh + (size_t)(nt*HH + j0 + grp)*HH;
#pragma unroll
        for(int kt=0; kt<4; kt++){
            int k0 = warp*64 + kt*16 + tig*2;
            float f0=wr[k0], f1=wr[k0+1], f2=wr[k0+8], f3=wr[k0+9];
            __half h0,l0,h1,l1,h2,l2,h3,l3;
            split_h(f0,h0,l0); split_h(f1,h1,l1); split_h(f2,h2,l2); split_h(f3,h3,l3);
            Bh[nt][kt][0]=pack_h2(h0,h1); Bh[nt][kt][1]=pack_h2(h2,h3);
            Bl[nt][kt][0]=pack_h2(l0,l1); Bl[nt][kt][1]=pack_h2(l2,l3);
        }
    }

    const int gb=tid>>3, gnr=tid&7;
    float br_=0.f,bz_=0.f,bn_=0.f;
    size_t woff=0;
    if(tid<256){
        br_=b_hh[j0+gnr]; bz_=b_hh[HH+j0+gnr]; bn_=b_hh[2*HH+j0+gnr];
        int j=j0+gnr, gkt=j>>4, c=j&15, mt=gb>>4, r=gb&15;
        int ln=(r&7)*4+((c>>1)&3), q=((r>>3)&1)+2*((c>>3)&1);
        woff=(((size_t)(gkt*2+mt))<<9) + ln*16 + q*4 + (c&1)*2;
    }

#pragma unroll 1
    for(int t=0; t<TT; t++){
        const uint8_t* pHiC=g_pHi[t&1];
        const uint8_t* pLoC=g_pLo[t&1];
        uint8_t* pHiN=g_pHi[(t+1)&1];
        uint8_t* pLoN=g_pLo[(t+1)&1];
        const float* cur32=(t&1)?g_hb:g_ha;
        float* nxt32=(t&1)?g_ha:g_hb;

        float xr=0.f,xz=0.f,xn=0.f,hold=0.f;
        if(tid<256){
            size_t gbase=((size_t)gb*TT+t)*G3+(j0+gnr);
            xr=__ldg(&gx[gbase]); xz=__ldg(&gx[gbase+HH]); xn=__ldg(&gx[gbase+2*HH]);
            hold=__ldcg(&cur32[gb*HH+j0+gnr]);
        }

#pragma unroll
        for(int mt=0; mt<2; mt++){
            uint4 Ah[4], Al[4];
#pragma unroll
            for(int kt=0; kt<4; kt++){
                int gkt=warp*4+kt;
                size_t off=(((size_t)(gkt*2+mt))<<9)+lane*16;
                Ah[kt]=ld_u128_cg(pHiC+off);
                Al[kt]=ld_u128_cg(pLoC+off);
            }
            float C[3][4];
#pragma unroll
            for(int nt=0;nt<3;nt++)
#pragma unroll
                for(int i=0;i<4;i++) C[nt][i]=0.f;
#pragma unroll
            for(int nt=0; nt<3; nt++){
#pragma unroll
                for(int kt=0; kt<4; kt++){
                    mma16816(C[nt], (const uint32_t*)&Ah[kt], Bh[nt][kt]);
                    mma16816(C[nt], (const uint32_t*)&Al[kt], Bh[nt][kt]);
                    mma16816(C[nt], (const uint32_t*)&Ah[kt], Bl[nt][kt]);
                }
            }
#pragma unroll
            for(int nt=0; nt<3; nt++){
                float* rb=&red[warp*768 + (mt*3+nt)*128];
                int p0=grp*8+tig*2;
                rb[p0]=C[nt][0]; rb[p0+1]=C[nt][1];
                rb[p0+64]=C[nt][2]; rb[p0+65]=C[nt][3];
            }
        }
        __syncthreads();

        if(tid<256){
            int mt=gb>>4, r=gb&15;
            float pr=0.f,pz=0.f,pn=0.f;
#pragma unroll
            for(int w=0; w<16; w++){
                int base=w*768 + mt*384 + r*8 + gnr;
                pr+=red[base];
                pz+=red[base+128];
                pn+=red[base+256];
            }
            float rr=1.f/(1.f+__expf(-(xr+pr+br_)));
            float zz=1.f/(1.f+__expf(-(xz+pz+bz_)));
            float nn=tanhf(xn+rr*(pn+bn_));
            float hnew=(1.f-zz)*nn+zz*hold;
            __stcg(&nxt32[gb*HH+j0+gnr],hnew);
            __half hi,lo; split_h(hnew,hi,lo);
            st_u16_cg(pHiN+woff, *(unsigned short*)&hi);
            st_u16_cg(pLoN+woff, *(unsigned short*)&lo);
            if(writeOut) out[((size_t)gb*TT+t)*HH+j0+gnr]=hnew;
        }

        __threadfence();
        __syncthreads();
        if(tid==0){
            atomicAdd(&g_bar,1u);
            unsigned target=nCta*(unsigned)(t+1);
            while(*((volatile unsigned*)&g_bar)<target){}
            __threadfence();
        }
        __syncthreads();
    }
}

// ---- FC ----
__global__ __launch_bounds__(256) void fc_kernel(
    const float* __restrict__ h, const float* __restrict__ w,
    const float* __restrict__ bias, float* __restrict__ outp)
{
    int gw=(int)((blockIdx.x*blockDim.x+threadIdx.x)>>5), lane=threadIdx.x&31;
    if(gw>=BB*DOUT) return;
    int m=gw>>8, o=gw&255;
    float acc=0.f;
#pragma unroll
    for(int i=0;i<8;i++){
        float4 hv=*(const float4*)&h[m*HH+i*128+lane*4];
        float4 wv=*(const float4*)&w[o*HH+i*128+lane*4];
        acc+=hv.x*wv.x+hv.y*wv.y+hv.z*wv.z+hv.w*wv.w;
    }
#pragma unroll
    for(int off=16;off>0;off>>=1) acc+=__shfl_xor_sync(0xffffffffu,acc,off);
    if(lane==0) outp[m*DOUT+o]=1.f/(1.f+__expf(-(acc+bias[o])));
}

extern "C" void kernel_launch(void* const* d_in, const int* in_sizes, int n_in,
                              void* d_out, int out_size)
{
    const float* input=(const float*)d_in[0];
    const float* w_ih0=(const float*)d_in[1];
    const float* w_hh0=(const float*)d_in[2];
    const float* b_ih0=(const float*)d_in[3];
    const float* b_hh0=(const float*)d_in[4];
    const float* w_ih1=(const float*)d_in[5];
    const float* w_hh1=(const float*)d_in[6];
    const float* b_ih1=(const float*)d_in[7];
    const float* b_hh1=(const float*)d_in[8];
    const float* fc_w=(const float*)d_in[9];
    const float* fc_b=(const float*)d_in[10];
    float* outp=(float*)d_out;

    float *gx,*out0,*ha; unsigned* bar; uint8_t *pHi,*pLo;
    cudaGetSymbolAddress((void**)&gx,g_gx);
    cudaGetSymbolAddress((void**)&out0,g_out0);
    cudaGetSymbolAddress((void**)&ha,g_ha);
    cudaGetSymbolAddress((void**)&bar,g_bar);
    cudaGetSymbolAddress((void**)&pHi,g_pHi);
    cudaGetSymbolAddress((void**)&pLo,g_pLo);

    dim3 ggrid(G3/128, MTOT/128);   // 24 x 128

    // Layer 0 input projection (HMMA, K=256)
    gemm_hmma<<<ggrid,256>>>(input,w_ih0,b_ih0,gx,MTOT,G3,DIN);

    // Layer 0 scan
    cudaMemsetAsync(ha,0,BB*HH*sizeof(float));
    cudaMemsetAsync(pHi,0,BB*HH*2);
    cudaMemsetAsync(pLo,0,BB*HH*2);
    cudaMemsetAsync(bar,0,sizeof(unsigned));
    gru_scan_hmma<<<128,512>>>(gx,w_hh0,b_hh0,out0,1);
    cudaMemcpyAsync(outp+BB*DOUT,ha,BB*HH*sizeof(float),cudaMemcpyDeviceToDevice);

    // Layer 1 input projection (HMMA, K=1024)
    gemm_hmma<<<ggrid,256>>>(out0,w_ih1,b_ih1,gx,MTOT,G3,HH);

    // Layer 1 scan
    cudaMemsetAsync(ha,0,BB*HH*sizeof(float));
    cudaMemsetAsync(pHi,0,BB*HH*2);
    cudaMemsetAsync(pLo,0,BB*HH*2);
    cudaMemsetAsync(bar,0,sizeof(unsigned));
    gru_scan_hmma<<<128,512>>>(gx,w_hh1,b_hh1,nullptr,0);
    cudaMemcpyAsync(outp+BB*DOUT+BB*HH,ha,BB*HH*sizeof(float),cudaMemcpyDeviceToDevice);

    fc_kernel<<<(BB*DOUT*32)/256,256>>>(ha,fc_w,fc_b,outp);
}

// round 8
// speedup vs baseline: 15.6819x; 1.0390x over previous
#include <cuda_runtime.h>
#include <cuda_fp16.h>
#include <cstdint>
#include <cstddef>

#define BB 32
#define TT 512
#define DIN 256
#define HH 1024
#define G3 3072
#define DOUT 256
#define MTOT (BB*TT)

// ---- static device scratch ----
__device__ float    g_gx[(size_t)MTOT*G3];
__device__ float    g_out0[(size_t)MTOT*HH];
__device__ float    g_ha[BB*HH];
__device__ float    g_hb[BB*HH];
__device__ uint8_t  g_pHi[2][BB*HH*2];
__device__ uint8_t  g_pLo[2][BB*HH*2];
__device__ __half   g_Ah[(size_t)MTOT*HH];   // pre-split A (hi), max K=1024
__device__ __half   g_Al[(size_t)MTOT*HH];   // pre-split A (lo)
__device__ __half   g_Wh[(size_t)G3*HH];     // pre-split W (hi)
__device__ __half   g_Wl[(size_t)G3*HH];     // pre-split W (lo)
__device__ unsigned g_bar;

// ---- helpers ----
__device__ __forceinline__ void mma16816(float* c, const uint32_t* a, const uint32_t* b){
    asm volatile("mma.sync.aligned.m16n8k16.row.col.f32.f16.f16.f32 "
        "{%0,%1,%2,%3}, {%4,%5,%6,%7}, {%8,%9}, {%0,%1,%2,%3};"
        : "+f"(c[0]),"+f"(c[1]),"+f"(c[2]),"+f"(c[3])
        : "r"(a[0]),"r"(a[1]),"r"(a[2]),"r"(a[3]),"r"(b[0]),"r"(b[1]));
}
__device__ __forceinline__ void split_h(float x, __half& hi, __half& lo){
    hi = __float2half_rn(x);
    lo = __float2half_rn(x - __half2float(hi));
}
__device__ __forceinline__ uint32_t pack_h2(__half a, __half b){
    __half2 v = __halves2half2(a, b);
    return *(uint32_t*)&v;
}
__device__ __forceinline__ void st_u16_cg(uint8_t* p, unsigned short v){
    asm volatile("st.global.cg.u16 [%0], %1;" :: "l"(p), "h"(v) : "memory");
}
__device__ __forceinline__ uint4 ld_u128_cg(const uint8_t* p){
    uint4 v;
    asm volatile("ld.global.cg.v4.u32 {%0,%1,%2,%3}, [%4];"
                 : "=r"(v.x),"=r"(v.y),"=r"(v.z),"=r"(v.w) : "l"(p));
    return v;
}
__device__ __forceinline__ void split4_h(float4 v, uint2& hi, uint2& lo){
    __half h0,l0,h1,l1,h2,l2,h3,l3;
    split_h(v.x,h0,l0); split_h(v.y,h1,l1); split_h(v.z,h2,l2); split_h(v.w,h3,l3);
    hi.x = pack_h2(h0,h1); hi.y = pack_h2(h2,h3);
    lo.x = pack_h2(l0,l1); lo.y = pack_h2(l2,l3);
}
__device__ __forceinline__ uint32_t smem_u32(const void* p){
    uint32_t a; asm("{ .reg .u64 t; cvta.to.shared.u64 t, %1; cvt.u32.u64 %0, t; }":"=r"(a):"l"(p)); return a; }
__device__ __forceinline__ void cp16(uint32_t sdst, const void* gsrc){
    asm volatile("cp.async.ca.shared.global [%0], [%1], 16;" :: "r"(sdst), "l"(gsrc)); }
__device__ __forceinline__ void cp_commit(){ asm volatile("cp.async.commit_group;" ::: "memory"); }
__device__ __forceinline__ void cp_wait1(){ asm volatile("cp.async.wait_group 1;" ::: "memory"); }
__device__ __forceinline__ void cp_wait0(){ asm volatile("cp.async.wait_group 0;" ::: "memory"); }

// ---------------------------------------------------------------------------
// Elementwise fp32 -> fp16 hi/lo split (4 elements per thread)
// ---------------------------------------------------------------------------
__global__ __launch_bounds__(256) void split_kernel(
    const float* __restrict__ X, __half* __restrict__ Xh,
    __half* __restrict__ Xl, int n4)
{
    int i = blockIdx.x*blockDim.x + threadIdx.x;
    if(i >= n4) return;
    float4 v = __ldg((const float4*)X + i);
    uint2 hi, lo; split4_h(v, hi, lo);
    *(uint2*)(Xh + (size_t)i*4) = hi;
    *(uint2*)(Xl + (size_t)i*4) = lo;
}

// ---------------------------------------------------------------------------
// HMMA GEMM on pre-split fp16: C = A @ W^T + bias. 3-term hi/lo.
// 256 thr = 8 warps (2m x 4n), tile 128x128, BK=32, cp.async double-buffer.
// ---------------------------------------------------------------------------
#define GP 40
#define TILE_H (128*GP)           // halves per tile
#define BUF_H  (4*TILE_H)         // Ah,Al,Bh,Bl
__global__ __launch_bounds__(256) void gemm_hmma16(
    const __half* __restrict__ Ah, const __half* __restrict__ Al,
    const __half* __restrict__ Wh, const __half* __restrict__ Wl,
    const float* __restrict__ bias, float* __restrict__ C, int M, int N, int K)
{
    extern __shared__ __half S[];   // [2][4][128*GP]
    const uint32_t sbase = smem_u32(S);

    const int tid=threadIdx.x, warp=tid>>5, lane=tid&31;
    const int grp=lane>>2, tig=lane&3;
    const int warpM=warp>>2, warpN=warp&3;
    const int m0=blockIdx.y*128, n0=blockIdx.x*128;

    float acc[4][4][4];
#pragma unroll
    for(int mt=0;mt<4;mt++)
#pragma unroll
        for(int nt=0;nt<4;nt++)
#pragma unroll
            for(int i=0;i<4;i++) acc[mt][nt][i]=0.f;

    const int nIter = K >> 5;

    // staging: 2048 16B-chunks per k-tile, 8 per thread
    auto stage = [&](int buf, int k0){
        const __half* srcs[4] = { Ah, Al, Wh, Wl };
#pragma unroll
        for(int i=0;i<8;i++){
            int id = i*256 + tid;
            int tile = id>>9, rem = id&511, row = rem>>2, c = rem&3;
            const __half* src = srcs[tile]
                + (size_t)(((tile<2)?m0:n0) + row)*K + k0 + c*8;
            uint32_t dst = sbase + (buf*BUF_H + tile*TILE_H + row*GP + c*8)*2;
            cp16(dst, src);
        }
    };

    stage(0, 0);
    cp_commit();

    for(int it=0; it<nIter; it++){
        if(it+1 < nIter){ stage((it+1)&1, (it+1)*32); cp_commit(); cp_wait1(); }
        else cp_wait0();
        __syncthreads();

        const __half* Ash = S + (it&1)*BUF_H;
        const __half* Asl = Ash + TILE_H;
        const __half* Bsh = Asl + TILE_H;
        const __half* Bsl = Bsh + TILE_H;

#pragma unroll
        for(int kc=0;kc<2;kc++){
            const int ko=kc*16+tig*2;
            uint32_t bh[4][2], bl[4][2];
#pragma unroll
            for(int nt=0;nt<4;nt++){
                int r=warpN*32+nt*8+grp;
                bh[nt][0]=*(uint32_t*)&Bsh[r*GP+ko];
                bh[nt][1]=*(uint32_t*)&Bsh[r*GP+ko+8];
                bl[nt][0]=*(uint32_t*)&Bsl[r*GP+ko];
                bl[nt][1]=*(uint32_t*)&Bsl[r*GP+ko+8];
            }
#pragma unroll
            for(int mt=0;mt<4;mt++){
                int r=warpM*64+mt*16+grp;
                uint32_t ah[4], al[4];
                ah[0]=*(uint32_t*)&Ash[r*GP+ko];
                ah[1]=*(uint32_t*)&Ash[(r+8)*GP+ko];
                ah[2]=*(uint32_t*)&Ash[r*GP+ko+8];
                ah[3]=*(uint32_t*)&Ash[(r+8)*GP+ko+8];
                al[0]=*(uint32_t*)&Asl[r*GP+ko];
                al[1]=*(uint32_t*)&Asl[(r+8)*GP+ko];
                al[2]=*(uint32_t*)&Asl[r*GP+ko+8];
                al[3]=*(uint32_t*)&Asl[(r+8)*GP+ko+8];
#pragma unroll
                for(int nt=0;nt<4;nt++){
                    mma16816(acc[mt][nt], ah, bh[nt]);
                    mma16816(acc[mt][nt], al, bh[nt]);
                    mma16816(acc[mt][nt], ah, bl[nt]);
                }
            }
        }
        __syncthreads();
    }

#pragma unroll
    for(int mt=0;mt<4;mt++){
        int r=m0+warpM*64+mt*16+grp;
#pragma unroll
        for(int nt=0;nt<4;nt++){
            int c=n0+warpN*32+nt*8+tig*2;
            float b0=bias[c], b1=bias[c+1];
            float2 v0={acc[mt][nt][0]+b0, acc[mt][nt][1]+b1};
            float2 v1={acc[mt][nt][2]+b0, acc[mt][nt][3]+b1};
            *(float2*)&C[(size_t)r*N+c]=v0;
            *(float2*)&C[(size_t)(r+8)*N+c]=v1;
        }
    }
}

// ---------------------------------------------------------------------------
// HMMA GRU scan (unchanged — verified 2.04us/step)
// ---------------------------------------------------------------------------
__global__ __launch_bounds__(512) void gru_scan_hmma(
    const float* __restrict__ gx, const float* __restrict__ w_hh,
    const float* __restrict__ b_hh, float* __restrict__ out, int writeOut)
{
    __shared__ float red[16*768];

    const int tid=threadIdx.x, warp=tid>>5, lane=tid&31, j0=blockIdx.x*8;
    const unsigned nCta=gridDim.x;
    const int grp=lane>>2, tig=lane&3;

    uint32_t Bh[3][4][2], Bl[3][4][2];
#pragma unroll
    for(int nt=0; nt<3; nt++){
        const float* wr = w_hh + (size_t)(nt*HH + j0 + grp)*HH;
#pragma unroll
        for(int kt=0; kt<4; kt++){
            int k0 = warp*64 + kt*16 + tig*2;
            float f0=wr[k0], f1=wr[k0+1], f2=wr[k0+8], f3=wr[k0+9];
            __half h0,l0,h1,l1,h2,l2,h3,l3;
            split_h(f0,h0,l0); split_h(f1,h1,l1); split_h(f2,h2,l2); split_h(f3,h3,l3);
            Bh[nt][kt][0]=pack_h2(h0,h1); Bh[nt][kt][1]=pack_h2(h2,h3);
            Bl[nt][kt][0]=pack_h2(l0,l1); Bl[nt][kt][1]=pack_h2(l2,l3);
        }
    }

    const int gb=tid>>3, gnr=tid&7;
    float br_=0.f,bz_=0.f,bn_=0.f;
    size_t woff=0;
    if(tid<256){
        br_=b_hh[j0+gnr]; bz_=b_hh[HH+j0+gnr]; bn_=b_hh[2*HH+j0+gnr];
        int j=j0+gnr, gkt=j>>4, c=j&15, mt=gb>>4, r=gb&15;
        int ln=(r&7)*4+((c>>1)&3), q=((r>>3)&1)+2*((c>>3)&1);
        woff=(((size_t)(gkt*2+mt))<<9) + ln*16 + q*4 + (c&1)*2;
    }

#pragma unroll 1
    for(int t=0; t<TT; t++){
        const uint8_t* pHiC=g_pHi[t&1];
        const uint8_t* pLoC=g_pLo[t&1];
        uint8_t* pHiN=g_pHi[(t+1)&1];
        uint8_t* pLoN=g_pLo[(t+1)&1];
        const float* cur32=(t&1)?g_hb:g_ha;
        float* nxt32=(t&1)?g_ha:g_hb;

        float xr=0.f,xz=0.f,xn=0.f,hold=0.f;
        if(tid<256){
            size_t gbase=((size_t)gb*TT+t)*G3+(j0+gnr);
            xr=__ldg(&gx[gbase]); xz=__ldg(&gx[gbase+HH]); xn=__ldg(&gx[gbase+2*HH]);
            hold=__ldcg(&cur32[gb*HH+j0+gnr]);
        }

#pragma unroll
        for(int mt=0; mt<2; mt++){
            uint4 Ah[4], Al[4];
#pragma unroll
            for(int kt=0; kt<4; kt++){
                int gkt=warp*4+kt;
                size_t off=(((size_t)(gkt*2+mt))<<9)+lane*16;
                Ah[kt]=ld_u128_cg(pHiC+off);
                Al[kt]=ld_u128_cg(pLoC+off);
            }
            float C[3][4];
#pragma unroll
            for(int nt=0;nt<3;nt++)
#pragma unroll
                for(int i=0;i<4;i++) C[nt][i]=0.f;
#pragma unroll
            for(int nt=0; nt<3; nt++){
#pragma unroll
                for(int kt=0; kt<4; kt++){
                    mma16816(C[nt], (const uint32_t*)&Ah[kt], Bh[nt][kt]);
                    mma16816(C[nt], (const uint32_t*)&Al[kt], Bh[nt][kt]);
                    mma16816(C[nt], (const uint32_t*)&Ah[kt], Bl[nt][kt]);
                }
            }
#pragma unroll
            for(int nt=0; nt<3; nt++){
                float* rb=&red[warp*768 + (mt*3+nt)*128];
                int p0=grp*8+tig*2;
                rb[p0]=C[nt][0]; rb[p0+1]=C[nt][1];
                rb[p0+64]=C[nt][2]; rb[p0+65]=C[nt][3];
            }
        }
        __syncthreads();

        if(tid<256){
            int mt=gb>>4, r=gb&15;
            float pr=0.f,pz=0.f,pn=0.f;
#pragma unroll
            for(int w=0; w<16; w++){
                int base=w*768 + mt*384 + r*8 + gnr;
                pr+=red[base];
                pz+=red[base+128];
                pn+=red[base+256];
            }
            float rr=1.f/(1.f+__expf(-(xr+pr+br_)));
            float zz=1.f/(1.f+__expf(-(xz+pz+bz_)));
            float nn=tanhf(xn+rr*(pn+bn_));
            float hnew=(1.f-zz)*nn+zz*hold;
            __stcg(&nxt32[gb*HH+j0+gnr],hnew);
            __half hi,lo; split_h(hnew,hi,lo);
            st_u16_cg(pHiN+woff, *(unsigned short*)&hi);
            st_u16_cg(pLoN+woff, *(unsigned short*)&lo);
            if(writeOut) out[((size_t)gb*TT+t)*HH+j0+gnr]=hnew;
        }

        __threadfence();
        __syncthreads();
        if(tid==0){
            atomicAdd(&g_bar,1u);
            unsigned target=nCta*(unsigned)(t+1);
            while(*((volatile unsigned*)&g_bar)<target){}
            __threadfence();
        }
        __syncthreads();
    }
}

// ---- FC ----
__global__ __launch_bounds__(256) void fc_kernel(
    const float* __restrict__ h, const float* __restrict__ w,
    const float* __restrict__ bias, float* __restrict__ outp)
{
    int gw=(int)((blockIdx.x*blockDim.x+threadIdx.x)>>5), lane=threadIdx.x&31;
    if(gw>=BB*DOUT) return;
    int m=gw>>8, o=gw&255;
    float acc=0.f;
#pragma unroll
    for(int i=0;i<8;i++){
        float4 hv=*(const float4*)&h[m*HH+i*128+lane*4];
        float4 wv=*(const float4*)&w[o*HH+i*128+lane*4];
        acc+=hv.x*wv.x+hv.y*wv.y+hv.z*wv.z+hv.w*wv.w;
    }
#pragma unroll
    for(int off=16;off>0;off>>=1) acc+=__shfl_xor_sync(0xffffffffu,acc,off);
    if(lane==0) outp[m*DOUT+o]=1.f/(1.f+__expf(-(acc+bias[o])));
}

extern "C" void kernel_launch(void* const* d_in, const int* in_sizes, int n_in,
                              void* d_out, int out_size)
{
    const float* input=(const float*)d_in[0];
    const float* w_ih0=(const float*)d_in[1];
    const float* w_hh0=(const float*)d_in[2];
    const float* b_ih0=(const float*)d_in[3];
    const float* b_hh0=(const float*)d_in[4];
    const float* w_ih1=(const float*)d_in[5];
    const float* w_hh1=(const float*)d_in[6];
    const float* b_ih1=(const float*)d_in[7];
    const float* b_hh1=(const float*)d_in[8];
    const float* fc_w=(const float*)d_in[9];
    const float* fc_b=(const float*)d_in[10];
    float* outp=(float*)d_out;

    float *gx,*out0,*ha; unsigned* bar; uint8_t *pHi,*pLo;
    __half *Ahp,*Alp,*Whp,*Wlp;
    cudaGetSymbolAddress((void**)&gx,g_gx);
    cudaGetSymbolAddress((void**)&out0,g_out0);
    cudaGetSymbolAddress((void**)&ha,g_ha);
    cudaGetSymbolAddress((void**)&bar,g_bar);
    cudaGetSymbolAddress((void**)&pHi,g_pHi);
    cudaGetSymbolAddress((void**)&pLo,g_pLo);
    cudaGetSymbolAddress((void**)&Ahp,g_Ah);
    cudaGetSymbolAddress((void**)&Alp,g_Al);
    cudaGetSymbolAddress((void**)&Whp,g_Wh);
    cudaGetSymbolAddress((void**)&Wlp,g_Wl);

    const int gemm_smem = 2*BUF_H*2;   // 81920 B
    cudaFuncSetAttribute(gemm_hmma16,
                         cudaFuncAttributeMaxDynamicSharedMemorySize, gemm_smem);

    dim3 ggrid(G3/128, MTOT/128);   // 24 x 128

    // ---- Layer 0: split inputs + weights, GEMM, scan ----
    split_kernel<<<(MTOT*DIN/4+255)/256,256>>>(input, Ahp, Alp, MTOT*DIN/4);
    split_kernel<<<(G3*DIN/4+255)/256,256>>>(w_ih0, Whp, Wlp, G3*DIN/4);
    gemm_hmma16<<<ggrid,256,gemm_smem>>>(Ahp,Alp,Whp,Wlp,b_ih0,gx,MTOT,G3,DIN);

    cudaMemsetAsync(ha,0,BB*HH*sizeof(float));
    cudaMemsetAsync(pHi,0,BB*HH*2);
    cudaMemsetAsync(pLo,0,BB*HH*2);
    cudaMemsetAsync(bar,0,sizeof(unsigned));
    gru_scan_hmma<<<128,512>>>(gx,w_hh0,b_hh0,out0,1);
    cudaMemcpyAsync(outp+BB*DOUT,ha,BB*HH*sizeof(float),cudaMemcpyDeviceToDevice);

    // ---- Layer 1 ----
    split_kernel<<<(MTOT*HH/4+255)/256,256>>>(out0, Ahp, Alp, MTOT*HH/4);
    split_kernel<<<(G3*HH/4+255)/256,256>>>(w_ih1, Whp, Wlp, G3*HH/4);
    gemm_hmma16<<<ggrid,256,gemm_smem>>>(Ahp,Alp,Whp,Wlp,b_ih1,gx,MTOT,G3,HH);

    cudaMemsetAsync(ha,0,BB*HH*sizeof(float));
    cudaMemsetAsync(pHi,0,BB*HH*2);
    cudaMemsetAsync(pLo,0,BB*HH*2);
    cudaMemsetAsync(bar,0,sizeof(unsigned));
    gru_scan_hmma<<<128,512>>>(gx,w_hh1,b_hh1,nullptr,0);
    cudaMemcpyAsync(outp+BB*DOUT+BB*HH,ha,BB*HH*sizeof(float),cudaMemcpyDeviceToDevice);

    fc_kernel<<<(BB*DOUT*32)/256,256>>>(ha,fc_w,fc_b,outp);
}

// round 9
// speedup vs baseline: 16.1652x; 1.0308x over previous
#include <cuda_runtime.h>
#include <cuda_fp16.h>
#include <cstdint>
#include <cstddef>

#define BB 32
#define TT 512
#define DIN 256
#define HH 1024
#define G3 3072
#define DOUT 256
#define MTOT (BB*TT)

// ---- static device scratch ----
__device__ float    g_gx[(size_t)MTOT*G3];
__device__ float    g_out0[(size_t)MTOT*HH];
__device__ float    g_ha[BB*HH];
__device__ float    g_hb[BB*HH];
__device__ uint8_t  g_pHi[2][BB*HH*2];
__device__ uint8_t  g_pLo[2][BB*HH*2];
__device__ uint8_t  g_AhF[(size_t)MTOT*HH*2];   // A fragments (hi)
__device__ uint8_t  g_AlF[(size_t)MTOT*HH*2];   // A fragments (lo)
__device__ uint8_t  g_BhF[(size_t)G3*HH*2];     // W fragments (hi)
__device__ uint8_t  g_BlF[(size_t)G3*HH*2];     // W fragments (lo)
__device__ unsigned g_bar;

// ---- helpers ----
__device__ __forceinline__ void mma16816(float* c, const uint32_t* a, const uint32_t* b){
    asm volatile("mma.sync.aligned.m16n8k16.row.col.f32.f16.f16.f32 "
        "{%0,%1,%2,%3}, {%4,%5,%6,%7}, {%8,%9}, {%0,%1,%2,%3};"
        : "+f"(c[0]),"+f"(c[1]),"+f"(c[2]),"+f"(c[3])
        : "r"(a[0]),"r"(a[1]),"r"(a[2]),"r"(a[3]),"r"(b[0]),"r"(b[1]));
}
__device__ __forceinline__ void split_h(float x, __half& hi, __half& lo){
    hi = __float2half_rn(x);
    lo = __float2half_rn(x - __half2float(hi));
}
__device__ __forceinline__ uint32_t pack_h2(__half a, __half b){
    __half2 v = __halves2half2(a, b);
    return *(uint32_t*)&v;
}
__device__ __forceinline__ void split2(float2 v, uint32_t& hi, uint32_t& lo){
    __half h0,l0,h1,l1;
    split_h(v.x,h0,l0); split_h(v.y,h1,l1);
    hi = pack_h2(h0,h1); lo = pack_h2(l0,l1);
}
__device__ __forceinline__ void st_u16_cg(uint8_t* p, unsigned short v){
    asm volatile("st.global.cg.u16 [%0], %1;" :: "l"(p), "h"(v) : "memory");
}
__device__ __forceinline__ uint4 ld_u128_cg(const uint8_t* p){
    uint4 v;
    asm volatile("ld.global.cg.v4.u32 {%0,%1,%2,%3}, [%4];"
                 : "=r"(v.x),"=r"(v.y),"=r"(v.z),"=r"(v.w) : "l"(p));
    return v;
}

// ---------------------------------------------------------------------------
// Split fp32 matrix into mma A-fragment order (hi/lo fp16).
// Fragment (tm,tk): 32 lanes x uint4 {a0,a1,a2,a3}; a0=(grp,tig*2 pair),
// a1=(grp+8,..), a2=(grp,+8 pair), a3=(grp+8,+8). idx=((tm*KT+tk)*32+lane).
// ---------------------------------------------------------------------------
__global__ __launch_bounds__(256) void splitA_frag(
    const float* __restrict__ X, uint8_t* __restrict__ Fh,
    uint8_t* __restrict__ Fl, int M, int K)
{
    int idx = blockIdx.x*256 + threadIdx.x;
    int KT = K >> 4;
    int total = (M >> 4) * KT * 32;
    if(idx >= total) return;
    int lane = idx & 31, tile = idx >> 5;
    int tk = tile % KT, tm = tile / KT;
    int grp = lane >> 2, tig = lane & 3;
    const float* p0 = X + (size_t)(tm*16+grp)*K + tk*16 + tig*2;
    const float* p1 = p0 + (size_t)8*K;
    float2 v0 = *(const float2*)p0;
    float2 v1 = *(const float2*)p1;
    float2 v2 = *(const float2*)(p0+8);
    float2 v3 = *(const float2*)(p1+8);
    uint4 hi, lo;
    split2(v0, hi.x, lo.x); split2(v1, hi.y, lo.y);
    split2(v2, hi.z, lo.z); split2(v3, hi.w, lo.w);
    *(uint4*)(Fh + (size_t)idx*16) = hi;
    *(uint4*)(Fl + (size_t)idx*16) = lo;
}

// B-fragment order: fragment (tn,tk): 32 lanes x uint2 {b0,b1};
// b0=(W[tn*8+grp][tk*16+tig*2] pair), b1=(+8 pair). idx=((tn*KT+tk)*32+lane).
__global__ __launch_bounds__(256) void splitB_frag(
    const float* __restrict__ W, uint8_t* __restrict__ Fh,
    uint8_t* __restrict__ Fl, int N, int K)
{
    int idx = blockIdx.x*256 + threadIdx.x;
    int KT = K >> 4;
    int total = (N >> 3) * KT * 32;
    if(idx >= total) return;
    int lane = idx & 31, tile = idx >> 5;
    int tk = tile % KT, tn = tile / KT;
    int grp = lane >> 2, tig = lane & 3;
    const float* p = W + (size_t)(tn*8+grp)*K + tk*16 + tig*2;
    float2 v0 = *(const float2*)p;
    float2 v1 = *(const float2*)(p+8);
    uint2 hi, lo;
    split2(v0, hi.x, lo.x); split2(v1, hi.y, lo.y);
    *(uint2*)(Fh + (size_t)idx*8) = hi;
    *(uint2*)(Fl + (size_t)idx*8) = lo;
}

// ---------------------------------------------------------------------------
// Fragment-resident HMMA GEMM: C[M,N] = A @ W^T + bias, 3-term hi/lo.
// Zero smem. 8 warps (2m x 4n), CTA tile 128x128, register double-buffer.
// Per k16-chunk per warp: 8 LDG.128 + 8 LDG.64 + 48 HMMA.
// ---------------------------------------------------------------------------
__global__ __launch_bounds__(256) void gemm_hmma_frag(
    const uint8_t* __restrict__ AhF, const uint8_t* __restrict__ AlF,
    const uint8_t* __restrict__ BhF, const uint8_t* __restrict__ BlF,
    const float* __restrict__ bias, float* __restrict__ C, int M, int N, int K)
{
    const int tid=threadIdx.x, warp=tid>>5, lane=tid&31;
    const int grp=lane>>2, tig=lane&3;
    const int warpM=warp>>2, warpN=warp&3;
    const int m0=blockIdx.y*128, n0=blockIdx.x*128;
    const int KT=K>>4;

    size_t aOff[4], bOff[4];
#pragma unroll
    for(int mt=0;mt<4;mt++)
        aOff[mt] = ((size_t)((m0>>4)+warpM*4+mt)*KT*32 + lane)*16;
#pragma unroll
    for(int nt=0;nt<4;nt++)
        bOff[nt] = ((size_t)((n0>>3)+warpN*4+nt)*KT*32 + lane)*8;

    float acc[4][4][4];
#pragma unroll
    for(int mt=0;mt<4;mt++)
#pragma unroll
        for(int nt=0;nt<4;nt++)
#pragma unroll
            for(int i=0;i<4;i++) acc[mt][nt][i]=0.f;

    uint4 AH[2][4], AL[2][4];
    uint2 BH[2][4], BL[2][4];

    auto load = [&](int tk, int buf){
        size_t ka = (size_t)tk*512, kb = (size_t)tk*256;
#pragma unroll
        for(int mt=0;mt<4;mt++){
            AH[buf][mt] = ld_u128_cg(AhF + aOff[mt] + ka);
            AL[buf][mt] = ld_u128_cg(AlF + aOff[mt] + ka);
        }
#pragma unroll
        for(int nt=0;nt<4;nt++){
            BH[buf][nt] = *(const uint2*)(BhF + bOff[nt] + kb);
            BL[buf][nt] = *(const uint2*)(BlF + bOff[nt] + kb);
        }
    };
    auto domma = [&](int buf){
#pragma unroll
        for(int mt=0;mt<4;mt++){
#pragma unroll
            for(int nt=0;nt<4;nt++){
                mma16816(acc[mt][nt], (const uint32_t*)&AH[buf][mt], (const uint32_t*)&BH[buf][nt]);
                mma16816(acc[mt][nt], (const uint32_t*)&AL[buf][mt], (const uint32_t*)&BH[buf][nt]);
                mma16816(acc[mt][nt], (const uint32_t*)&AH[buf][mt], (const uint32_t*)&BL[buf][nt]);
            }
        }
    };

    load(0, 0);
    for(int tk=0; tk<KT; tk+=2){       // KT is even (16 or 64)
        load(tk+1, 1);
        domma(0);
        if(tk+2 < KT) load(tk+2, 0);
        domma(1);
    }

#pragma unroll
    for(int mt=0;mt<4;mt++){
        int r=m0+warpM*64+mt*16+grp;
#pragma unroll
        for(int nt=0;nt<4;nt++){
            int c=n0+warpN*32+nt*8+tig*2;
            float b0=bias[c], b1=bias[c+1];
            float2 v0={acc[mt][nt][0]+b0, acc[mt][nt][1]+b1};
            float2 v1={acc[mt][nt][2]+b0, acc[mt][nt][3]+b1};
            *(float2*)&C[(size_t)r*N+c]=v0;
            *(float2*)&C[(size_t)(r+8)*N+c]=v1;
        }
    }
}

// ---------------------------------------------------------------------------
// HMMA GRU scan (unchanged — verified 2.07us/step)
// ---------------------------------------------------------------------------
__global__ __launch_bounds__(512) void gru_scan_hmma(
    const float* __restrict__ gx, const float* __restrict__ w_hh,
    const float* __restrict__ b_hh, float* __restrict__ out, int writeOut)
{
    __shared__ float red[16*768];

    const int tid=threadIdx.x, warp=tid>>5, lane=tid&31, j0=blockIdx.x*8;
    const unsigned nCta=gridDim.x;
    const int grp=lane>>2, tig=lane&3;

    uint32_t Bh[3][4][2], Bl[3][4][2];
#pragma unroll
    for(int nt=0; nt<3; nt++){
        const float* wr = w_hh + (size_t)(nt*HH + j0 + grp)*HH;
#pragma unroll
        for(int kt=0; kt<4; kt++){
            int k0 = warp*64 + kt*16 + tig*2;
            float f0=wr[k0], f1=wr[k0+1], f2=wr[k0+8], f3=wr[k0+9];
            __half h0,l0,h1,l1,h2,l2,h3,l3;
            split_h(f0,h0,l0); split_h(f1,h1,l1); split_h(f2,h2,l2); split_h(f3,h3,l3);
            Bh[nt][kt][0]=pack_h2(h0,h1); Bh[nt][kt][1]=pack_h2(h2,h3);
            Bl[nt][kt][0]=pack_h2(l0,l1); Bl[nt][kt][1]=pack_h2(l2,l3);
        }
    }

    const int gb=tid>>3, gnr=tid&7;
    float br_=0.f,bz_=0.f,bn_=0.f;
    size_t woff=0;
    if(tid<256){
        br_=b_hh[j0+gnr]; bz_=b_hh[HH+j0+gnr]; bn_=b_hh[2*HH+j0+gnr];
        int j=j0+gnr, gkt=j>>4, c=j&15, mt=gb>>4, r=gb&15;
        int ln=(r&7)*4+((c>>1)&3), q=((r>>3)&1)+2*((c>>3)&1);
        woff=(((size_t)(gkt*2+mt))<<9) + ln*16 + q*4 + (c&1)*2;
    }

#pragma unroll 1
    for(int t=0; t<TT; t++){
        const uint8_t* pHiC=g_pHi[t&1];
        const uint8_t* pLoC=g_pLo[t&1];
        uint8_t* pHiN=g_pHi[(t+1)&1];
        uint8_t* pLoN=g_pLo[(t+1)&1];
        const float* cur32=(t&1)?g_hb:g_ha;
        float* nxt32=(t&1)?g_ha:g_hb;

        float xr=0.f,xz=0.f,xn=0.f,hold=0.f;
        if(tid<256){
            size_t gbase=((size_t)gb*TT+t)*G3+(j0+gnr);
            xr=__ldg(&gx[gbase]); xz=__ldg(&gx[gbase+HH]); xn=__ldg(&gx[gbase+2*HH]);
            hold=__ldcg(&cur32[gb*HH+j0+gnr]);
        }

#pragma unroll
        for(int mt=0; mt<2; mt++){
            uint4 Ah[4], Al[4];
#pragma unroll
            for(int kt=0; kt<4; kt++){
                int gkt=warp*4+kt;
                size_t off=(((size_t)(gkt*2+mt))<<9)+lane*16;
                Ah[kt]=ld_u128_cg(pHiC+off);
                Al[kt]=ld_u128_cg(pLoC+off);
            }
            float C[3][4];
#pragma unroll
            for(int nt=0;nt<3;nt++)
#pragma unroll
                for(int i=0;i<4;i++) C[nt][i]=0.f;
#pragma unroll
            for(int nt=0; nt<3; nt++){
#pragma unroll
                for(int kt=0; kt<4; kt++){
                    mma16816(C[nt], (const uint32_t*)&Ah[kt], Bh[nt][kt]);
                    mma16816(C[nt], (const uint32_t*)&Al[kt], Bh[nt][kt]);
                    mma16816(C[nt], (const uint32_t*)&Ah[kt], Bl[nt][kt]);
                }
            }
#pragma unroll
            for(int nt=0; nt<3; nt++){
                float* rb=&red[warp*768 + (mt*3+nt)*128];
                int p0=grp*8+tig*2;
                rb[p0]=C[nt][0]; rb[p0+1]=C[nt][1];
                rb[p0+64]=C[nt][2]; rb[p0+65]=C[nt][3];
            }
        }
        __syncthreads();

        if(tid<256){
            int mt=gb>>4, r=gb&15;
            float pr=0.f,pz=0.f,pn=0.f;
#pragma unroll
            for(int w=0; w<16; w++){
                int base=w*768 + mt*384 + r*8 + gnr;
                pr+=red[base];
                pz+=red[base+128];
                pn+=red[base+256];
            }
            float rr=1.f/(1.f+__expf(-(xr+pr+br_)));
            float zz=1.f/(1.f+__expf(-(xz+pz+bz_)));
            float nn=tanhf(xn+rr*(pn+bn_));
            float hnew=(1.f-zz)*nn+zz*hold;
            __stcg(&nxt32[gb*HH+j0+gnr],hnew);
            __half hi,lo; split_h(hnew,hi,lo);
            st_u16_cg(pHiN+woff, *(unsigned short*)&hi);
            st_u16_cg(pLoN+woff, *(unsigned short*)&lo);
            if(writeOut) out[((size_t)gb*TT+t)*HH+j0+gnr]=hnew;
        }

        __threadfence();
        __syncthreads();
        if(tid==0){
            atomicAdd(&g_bar,1u);
            unsigned target=nCta*(unsigned)(t+1);
            while(*((volatile unsigned*)&g_bar)<target){}
            __threadfence();
        }
        __syncthreads();
    }
}

// ---- FC ----
__global__ __launch_bounds__(256) void fc_kernel(
    const float* __restrict__ h, const float* __restrict__ w,
    const float* __restrict__ bias, float* __restrict__ outp)
{
    int gw=(int)((blockIdx.x*blockDim.x+threadIdx.x)>>5), lane=threadIdx.x&31;
    if(gw>=BB*DOUT) return;
    int m=gw>>8, o=gw&255;
    float acc=0.f;
#pragma unroll
    for(int i=0;i<8;i++){
        float4 hv=*(const float4*)&h[m*HH+i*128+lane*4];
        float4 wv=*(const float4*)&w[o*HH+i*128+lane*4];
        acc+=hv.x*wv.x+hv.y*wv.y+hv.z*wv.z+hv.w*wv.w;
    }
#pragma unroll
    for(int off=16;off>0;off>>=1) acc+=__shfl_xor_sync(0xffffffffu,acc,off);
    if(lane==0) outp[m*DOUT+o]=1.f/(1.f+__expf(-(acc+bias[o])));
}

extern "C" void kernel_launch(void* const* d_in, const int* in_sizes, int n_in,
                              void* d_out, int out_size)
{
    const float* input=(const float*)d_in[0];
    const float* w_ih0=(const float*)d_in[1];
    const float* w_hh0=(const float*)d_in[2];
    const float* b_ih0=(const float*)d_in[3];
    const float* b_hh0=(const float*)d_in[4];
    const float* w_ih1=(const float*)d_in[5];
    const float* w_hh1=(const float*)d_in[6];
    const float* b_ih1=(const float*)d_in[7];
    const float* b_hh1=(const float*)d_in[8];
    const float* fc_w=(const float*)d_in[9];
    const float* fc_b=(const float*)d_in[10];
    float* outp=(float*)d_out;

    float *gx,*out0,*ha; unsigned* bar; uint8_t *pHi,*pLo,*AhF,*AlF,*BhF,*BlF;
    cudaGetSymbolAddress((void**)&gx,g_gx);
    cudaGetSymbolAddress((void**)&out0,g_out0);
    cudaGetSymbolAddress((void**)&ha,g_ha);
    cudaGetSymbolAddress((void**)&bar,g_bar);
    cudaGetSymbolAddress((void**)&pHi,g_pHi);
    cudaGetSymbolAddress((void**)&pLo,g_pLo);
    cudaGetSymbolAddress((void**)&AhF,g_AhF);
    cudaGetSymbolAddress((void**)&AlF,g_AlF);
    cudaGetSymbolAddress((void**)&BhF,g_BhF);
    cudaGetSymbolAddress((void**)&BlF,g_BlF);

    dim3 ggrid(G3/128, MTOT/128);   // 24 x 128

    // ---- Layer 0: split to fragments, GEMM, scan ----
    {
        int tA = (MTOT>>4)*(DIN>>4)*32;
        int tB = (G3>>3)*(DIN>>4)*32;
        splitA_frag<<<(tA+255)/256,256>>>(input, AhF, AlF, MTOT, DIN);
        splitB_frag<<<(tB+255)/256,256>>>(w_ih0, BhF, BlF, G3, DIN);
    }
    gemm_hmma_frag<<<ggrid,256>>>(AhF,AlF,BhF,BlF,b_ih0,gx,MTOT,G3,DIN);

    cudaMemsetAsync(ha,0,BB*HH*sizeof(float));
    cudaMemsetAsync(pHi,0,BB*HH*2);
    cudaMemsetAsync(pLo,0,BB*HH*2);
    cudaMemsetAsync(bar,0,sizeof(unsigned));
    gru_scan_hmma<<<128,512>>>(gx,w_hh0,b_hh0,out0,1);
    cudaMemcpyAsync(outp+BB*DOUT,ha,BB*HH*sizeof(float),cudaMemcpyDeviceToDevice);

    // ---- Layer 1 ----
    {
        int tA = (MTOT>>4)*(HH>>4)*32;
        int tB = (G3>>3)*(HH>>4)*32;
        splitA_frag<<<(tA+255)/256,256>>>(out0, AhF, AlF, MTOT, HH);
        splitB_frag<<<(tB+255)/256,256>>>(w_ih1, BhF, BlF, G3, HH);
    }
    gemm_hmma_frag<<<ggrid,256>>>(AhF,AlF,BhF,BlF,b_ih1,gx,MTOT,G3,HH);

    cudaMemsetAsync(ha,0,BB*HH*sizeof(float));
    cudaMemsetAsync(pHi,0,BB*HH*2);
    cudaMemsetAsync(pLo,0,BB*HH*2);
    cudaMemsetAsync(bar,0,sizeof(unsigned));
    gru_scan_hmma<<<128,512>>>(gx,w_hh1,b_hh1,nullptr,0);
    cudaMemcpyAsync(outp+BB*DOUT+BB*HH,ha,BB*HH*sizeof(float),cudaMemcpyDeviceToDevice);

    fc_kernel<<<(BB*DOUT*32)/256,256>>>(ha,fc_w,fc_b,outp);
}

// round 10
// speedup vs baseline: 16.7919x; 1.0388x over previous
#include <cuda_runtime.h>
#include <cuda_fp16.h>
#include <cstdint>
#include <cstddef>

#define BB 32
#define TT 512
#define DIN 256
#define HH 1024
#define G3 3072
#define DOUT 256
#define MTOT (BB*TT)

// ---- static device scratch ----
__device__ float    g_gx[(size_t)MTOT*G3];
__device__ float    g_out0[(size_t)MTOT*HH];
__device__ float    g_ha[BB*HH];
__device__ float    g_hb[BB*HH];
__device__ uint8_t  g_pHi[2][BB*HH*2];          // h hi halves, A-fragment order
__device__ uint8_t  g_AhF[(size_t)MTOT*HH*2];   // A fragments (hi)
__device__ uint8_t  g_BhF[(size_t)G3*HH*2];     // W fragments (hi)
__device__ uint8_t  g_BlF[(size_t)G3*HH*2];     // W fragments (lo)
__device__ unsigned g_bar;

// ---- helpers ----
__device__ __forceinline__ void mma16816(float* c, const uint32_t* a, const uint32_t* b){
    asm volatile("mma.sync.aligned.m16n8k16.row.col.f32.f16.f16.f32 "
        "{%0,%1,%2,%3}, {%4,%5,%6,%7}, {%8,%9}, {%0,%1,%2,%3};"
        : "+f"(c[0]),"+f"(c[1]),"+f"(c[2]),"+f"(c[3])
        : "r"(a[0]),"r"(a[1]),"r"(a[2]),"r"(a[3]),"r"(b[0]),"r"(b[1]));
}
__device__ __forceinline__ void split_h(float x, __half& hi, __half& lo){
    hi = __float2half_rn(x);
    lo = __float2half_rn(x - __half2float(hi));
}
__device__ __forceinline__ uint32_t pack_h2(__half a, __half b){
    __half2 v = __halves2half2(a, b);
    return *(uint32_t*)&v;
}
__device__ __forceinline__ void split2(float2 v, uint32_t& hi, uint32_t& lo){
    __half h0,l0,h1,l1;
    split_h(v.x,h0,l0); split_h(v.y,h1,l1);
    hi = pack_h2(h0,h1); lo = pack_h2(l0,l1);
}
__device__ __forceinline__ uint32_t cvt2_hi(float2 v){
    return pack_h2(__float2half_rn(v.x), __float2half_rn(v.y));
}
__device__ __forceinline__ void st_u16_cg(uint8_t* p, unsigned short v){
    asm volatile("st.global.cg.u16 [%0], %1;" :: "l"(p), "h"(v) : "memory");
}
__device__ __forceinline__ uint4 ld_u128_cg(const uint8_t* p){
    uint4 v;
    asm volatile("ld.global.cg.v4.u32 {%0,%1,%2,%3}, [%4];"
                 : "=r"(v.x),"=r"(v.y),"=r"(v.z),"=r"(v.w) : "l"(p));
    return v;
}

// ---------------------------------------------------------------------------
// Split fp32 matrix into mma A-fragment order, HI halves only.
// Fragment (tm,tk): 32 lanes x uint4; idx=((tm*KT+tk)*32+lane).
// ---------------------------------------------------------------------------
__global__ __launch_bounds__(256) void splitA_frag(
    const float* __restrict__ X, uint8_t* __restrict__ Fh, int M, int K)
{
    int idx = blockIdx.x*256 + threadIdx.x;
    int KT = K >> 4;
    int total = (M >> 4) * KT * 32;
    if(idx >= total) return;
    int lane = idx & 31, tile = idx >> 5;
    int tk = tile % KT, tm = tile / KT;
    int grp = lane >> 2, tig = lane & 3;
    const float* p0 = X + (size_t)(tm*16+grp)*K + tk*16 + tig*2;
    const float* p1 = p0 + (size_t)8*K;
    uint4 hi;
    hi.x = cvt2_hi(*(const float2*)p0);
    hi.y = cvt2_hi(*(const float2*)p1);
    hi.z = cvt2_hi(*(const float2*)(p0+8));
    hi.w = cvt2_hi(*(const float2*)(p1+8));
    *(uint4*)(Fh + (size_t)idx*16) = hi;
}

// B-fragment order (hi + lo): fragment (tn,tk): 32 lanes x uint2.
__global__ __launch_bounds__(256) void splitB_frag(
    const float* __restrict__ W, uint8_t* __restrict__ Fh,
    uint8_t* __restrict__ Fl, int N, int K)
{
    int idx = blockIdx.x*256 + threadIdx.x;
    int KT = K >> 4;
    int total = (N >> 3) * KT * 32;
    if(idx >= total) return;
    int lane = idx & 31, tile = idx >> 5;
    int tk = tile % KT, tn = tile / KT;
    int grp = lane >> 2, tig = lane & 3;
    const float* p = W + (size_t)(tn*8+grp)*K + tk*16 + tig*2;
    float2 v0 = *(const float2*)p;
    float2 v1 = *(const float2*)(p+8);
    uint2 hi, lo;
    split2(v0, hi.x, lo.x); split2(v1, hi.y, lo.y);
    *(uint2*)(Fh + (size_t)idx*8) = hi;
    *(uint2*)(Fl + (size_t)idx*8) = lo;
}

// ---------------------------------------------------------------------------
// Fragment-resident HMMA GEMM, 2-term (Ah*Bh + Ah*Bl). Zero smem.
// 8 warps (2m x 4n), CTA tile 128x128, register double-buffer, L1-cached loads.
// ---------------------------------------------------------------------------
__global__ __launch_bounds__(256) void gemm_hmma_frag(
    const uint8_t* __restrict__ AhF,
    const uint8_t* __restrict__ BhF, const uint8_t* __restrict__ BlF,
    const float* __restrict__ bias, float* __restrict__ C, int M, int N, int K)
{
    const int tid=threadIdx.x, warp=tid>>5, lane=tid&31;
    const int grp=lane>>2, tig=lane&3;
    const int warpM=warp>>2, warpN=warp&3;
    const int m0=blockIdx.y*128, n0=blockIdx.x*128;
    const int KT=K>>4;

    const uint4* aBase[4];
    const uint2* bhBase[4];
    const uint2* blBase[4];
#pragma unroll
    for(int mt=0;mt<4;mt++)
        aBase[mt] = (const uint4*)(AhF + ((size_t)((m0>>4)+warpM*4+mt)*KT*32 + lane)*16);
#pragma unroll
    for(int nt=0;nt<4;nt++){
        size_t o = ((size_t)((n0>>3)+warpN*4+nt)*KT*32 + lane)*8;
        bhBase[nt] = (const uint2*)(BhF + o);
        blBase[nt] = (const uint2*)(BlF + o);
    }

    float acc[4][4][4];
#pragma unroll
    for(int mt=0;mt<4;mt++)
#pragma unroll
        for(int nt=0;nt<4;nt++)
#pragma unroll
            for(int i=0;i<4;i++) acc[mt][nt][i]=0.f;

    uint4 AH[2][4];
    uint2 BH[2][4], BL[2][4];

    auto load = [&](int tk, int buf){
#pragma unroll
        for(int mt=0;mt<4;mt++)
            AH[buf][mt] = __ldg(aBase[mt] + (size_t)tk*32);
#pragma unroll
        for(int nt=0;nt<4;nt++){
            BH[buf][nt] = __ldg(bhBase[nt] + (size_t)tk*32);
            BL[buf][nt] = __ldg(blBase[nt] + (size_t)tk*32);
        }
    };
    auto domma = [&](int buf){
#pragma unroll
        for(int mt=0;mt<4;mt++){
#pragma unroll
            for(int nt=0;nt<4;nt++){
                mma16816(acc[mt][nt], (const uint32_t*)&AH[buf][mt], (const uint32_t*)&BH[buf][nt]);
                mma16816(acc[mt][nt], (const uint32_t*)&AH[buf][mt], (const uint32_t*)&BL[buf][nt]);
            }
        }
    };

    load(0, 0);
    for(int tk=0; tk<KT; tk+=2){       // KT even (16 or 64)
        load(tk+1, 1);
        domma(0);
        if(tk+2 < KT) load(tk+2, 0);
        domma(1);
    }

#pragma unroll
    for(int mt=0;mt<4;mt++){
        int r=m0+warpM*64+mt*16+grp;
#pragma unroll
        for(int nt=0;nt<4;nt++){
            int c=n0+warpN*32+nt*8+tig*2;
            float b0=bias[c], b1=bias[c+1];
            float2 v0={acc[mt][nt][0]+b0, acc[mt][nt][1]+b1};
            float2 v1={acc[mt][nt][2]+b0, acc[mt][nt][3]+b1};
            *(float2*)&C[(size_t)r*N+c]=v0;
            *(float2*)&C[(size_t)(r+8)*N+c]=v1;
        }
    }
}

// ---------------------------------------------------------------------------
// HMMA GRU scan, 2-term: pre = h_hi*(Wh + Wl). h stored hi-only in fragment
// order -> per-step h broadcast halves to 8MB chip-wide.
// ---------------------------------------------------------------------------
__global__ __launch_bounds__(512) void gru_scan_hmma(
    const float* __restrict__ gx, const float* __restrict__ w_hh,
    const float* __restrict__ b_hh, float* __restrict__ out, int writeOut)
{
    __shared__ float red[16*768];

    const int tid=threadIdx.x, warp=tid>>5, lane=tid&31, j0=blockIdx.x*8;
    const unsigned nCta=gridDim.x;
    const int grp=lane>>2, tig=lane&3;

    uint32_t Bh[3][4][2], Bl[3][4][2];
#pragma unroll
    for(int nt=0; nt<3; nt++){
        const float* wr = w_hh + (size_t)(nt*HH + j0 + grp)*HH;
#pragma unroll
        for(int kt=0; kt<4; kt++){
            int k0 = warp*64 + kt*16 + tig*2;
            float f0=wr[k0], f1=wr[k0+1], f2=wr[k0+8], f3=wr[k0+9];
            __half h0,l0,h1,l1,h2,l2,h3,l3;
            split_h(f0,h0,l0); split_h(f1,h1,l1); split_h(f2,h2,l2); split_h(f3,h3,l3);
            Bh[nt][kt][0]=pack_h2(h0,h1); Bh[nt][kt][1]=pack_h2(h2,h3);
            Bl[nt][kt][0]=pack_h2(l0,l1); Bl[nt][kt][1]=pack_h2(l2,l3);
        }
    }

    const int gb=tid>>3, gnr=tid&7;
    float br_=0.f,bz_=0.f,bn_=0.f;
    size_t woff=0;
    if(tid<256){
        br_=b_hh[j0+gnr]; bz_=b_hh[HH+j0+gnr]; bn_=b_hh[2*HH+j0+gnr];
        int j=j0+gnr, gkt=j>>4, c=j&15, mt=gb>>4, r=gb&15;
        int ln=(r&7)*4+((c>>1)&3), q=((r>>3)&1)+2*((c>>3)&1);
        woff=(((size_t)(gkt*2+mt))<<9) + ln*16 + q*4 + (c&1)*2;
    }

#pragma unroll 1
    for(int t=0; t<TT; t++){
        const uint8_t* pHiC=g_pHi[t&1];
        uint8_t* pHiN=g_pHi[(t+1)&1];
        const float* cur32=(t&1)?g_hb:g_ha;
        float* nxt32=(t&1)?g_ha:g_hb;

        float xr=0.f,xz=0.f,xn=0.f,hold=0.f;
        if(tid<256){
            size_t gbase=((size_t)gb*TT+t)*G3+(j0+gnr);
            xr=__ldg(&gx[gbase]); xz=__ldg(&gx[gbase+HH]); xn=__ldg(&gx[gbase+2*HH]);
            hold=__ldcg(&cur32[gb*HH+j0+gnr]);
        }

#pragma unroll
        for(int mt=0; mt<2; mt++){
            uint4 Ah[4];
#pragma unroll
            for(int kt=0; kt<4; kt++){
                int gkt=warp*4+kt;
                size_t off=(((size_t)(gkt*2+mt))<<9)+lane*16;
                Ah[kt]=ld_u128_cg(pHiC+off);
            }
            float C[3][4];
#pragma unroll
            for(int nt=0;nt<3;nt++)
#pragma unroll
                for(int i=0;i<4;i++) C[nt][i]=0.f;
#pragma unroll
            for(int nt=0; nt<3; nt++){
#pragma unroll
                for(int kt=0; kt<4; kt++){
                    mma16816(C[nt], (const uint32_t*)&Ah[kt], Bh[nt][kt]);
                    mma16816(C[nt], (const uint32_t*)&Ah[kt], Bl[nt][kt]);
                }
            }
#pragma unroll
            for(int nt=0; nt<3; nt++){
                float* rb=&red[warp*768 + (mt*3+nt)*128];
                int p0=grp*8+tig*2;
                rb[p0]=C[nt][0]; rb[p0+1]=C[nt][1];
                rb[p0+64]=C[nt][2]; rb[p0+65]=C[nt][3];
            }
        }
        __syncthreads();

        if(tid<256){
            int mt=gb>>4, r=gb&15;
            float pr=0.f,pz=0.f,pn=0.f;
#pragma unroll
            for(int w=0; w<16; w++){
                int base=w*768 + mt*384 + r*8 + gnr;
                pr+=red[base];
                pz+=red[base+128];
                pn+=red[base+256];
            }
            float rr=1.f/(1.f+__expf(-(xr+pr+br_)));
            float zz=1.f/(1.f+__expf(-(xz+pz+bz_)));
            float nn=tanhf(xn+rr*(pn+bn_));
            float hnew=(1.f-zz)*nn+zz*hold;
            __stcg(&nxt32[gb*HH+j0+gnr],hnew);
            __half hi=__float2half_rn(hnew);
            st_u16_cg(pHiN+woff, *(unsigned short*)&hi);
            if(writeOut) out[((size_t)gb*TT+t)*HH+j0+gnr]=hnew;
        }

        __threadfence();
        __syncthreads();
        if(tid==0){
            atomicAdd(&g_bar,1u);
            unsigned target=nCta*(unsigned)(t+1);
            while(*((volatile unsigned*)&g_bar)<target){}
            __threadfence();
        }
        __syncthreads();
    }
}

// ---- FC ----
__global__ __launch_bounds__(256) void fc_kernel(
    const float* __restrict__ h, const float* __restrict__ w,
    const float* __restrict__ bias, float* __restrict__ outp)
{
    int gw=(int)((blockIdx.x*blockDim.x+threadIdx.x)>>5), lane=threadIdx.x&31;
    if(gw>=BB*DOUT) return;
    int m=gw>>8, o=gw&255;
    float acc=0.f;
#pragma unroll
    for(int i=0;i<8;i++){
        float4 hv=*(const float4*)&h[m*HH+i*128+lane*4];
        float4 wv=*(const float4*)&w[o*HH+i*128+lane*4];
        acc+=hv.x*wv.x+hv.y*wv.y+hv.z*wv.z+hv.w*wv.w;
    }
#pragma unroll
    for(int off=16;off>0;off>>=1) acc+=__shfl_xor_sync(0xffffffffu,acc,off);
    if(lane==0) outp[m*DOUT+o]=1.f/(1.f+__expf(-(acc+bias[o])));
}

extern "C" void kernel_launch(void* const* d_in, const int* in_sizes, int n_in,
                              void* d_out, int out_size)
{
    const float* input=(const float*)d_in[0];
    const float* w_ih0=(const float*)d_in[1];
    const float* w_hh0=(const float*)d_in[2];
    const float* b_ih0=(const float*)d_in[3];
    const float* b_hh0=(const float*)d_in[4];
    const float* w_ih1=(const float*)d_in[5];
    const float* w_hh1=(const float*)d_in[6];
    const float* b_ih1=(const float*)d_in[7];
    const float* b_hh1=(const float*)d_in[8];
    const float* fc_w=(const float*)d_in[9];
    const float* fc_b=(const float*)d_in[10];
    float* outp=(float*)d_out;

    float *gx,*out0,*ha; unsigned* bar; uint8_t *pHi,*AhF,*BhF,*BlF;
    cudaGetSymbolAddress((void**)&gx,g_gx);
    cudaGetSymbolAddress((void**)&out0,g_out0);
    cudaGetSymbolAddress((void**)&ha,g_ha);
    cudaGetSymbolAddress((void**)&bar,g_bar);
    cudaGetSymbolAddress((void**)&pHi,g_pHi);
    cudaGetSymbolAddress((void**)&AhF,g_AhF);
    cudaGetSymbolAddress((void**)&BhF,g_BhF);
    cudaGetSymbolAddress((void**)&BlF,g_BlF);

    dim3 ggrid(G3/128, MTOT/128);   // 24 x 128

    // ---- Layer 0 ----
    {
        int tA = (MTOT>>4)*(DIN>>4)*32;
        int tB = (G3>>3)*(DIN>>4)*32;
        splitA_frag<<<(tA+255)/256,256>>>(input, AhF, MTOT, DIN);
        splitB_frag<<<(tB+255)/256,256>>>(w_ih0, BhF, BlF, G3, DIN);
    }
    gemm_hmma_frag<<<ggrid,256>>>(AhF,BhF,BlF,b_ih0,gx,MTOT,G3,DIN);

    cudaMemsetAsync(ha,0,BB*HH*sizeof(float));
    cudaMemsetAsync(pHi,0,BB*HH*2);
    cudaMemsetAsync(bar,0,sizeof(unsigned));
    gru_scan_hmma<<<128,512>>>(gx,w_hh0,b_hh0,out0,1);
    cudaMemcpyAsync(outp+BB*DOUT,ha,BB*HH*sizeof(float),cudaMemcpyDeviceToDevice);

    // ---- Layer 1 ----
    {
        int tA = (MTOT>>4)*(HH>>4)*32;
        int tB = (G3>>3)*(HH>>4)*32;
        splitA_frag<<<(tA+255)/256,256>>>(out0, AhF, MTOT, HH);
        splitB_frag<<<(tB+255)/256,256>>>(w_ih1, BhF, BlF, G3, HH);
    }
    gemm_hmma_frag<<<ggrid,256>>>(AhF,BhF,BlF,b_ih1,gx,MTOT,G3,HH);

    cudaMemsetAsync(ha,0,BB*HH*sizeof(float));
    cudaMemsetAsync(pHi,0,BB*HH*2);
    cudaMemsetAsync(bar,0,sizeof(unsigned));
    gru_scan_hmma<<<128,512>>>(gx,w_hh1,b_hh1,nullptr,0);
    cudaMemcpyAsync(outp+BB*DOUT+BB*HH,ha,BB*HH*sizeof(float),cudaMemcpyDeviceToDevice);

    fc_kernel<<<(BB*DOUT*32)/256,256>>>(ha,fc_w,fc_b,outp);
}